// round 1
// baseline (speedup 1.0000x reference)
#include <cuda_runtime.h>
#include <math.h>
#include <stdint.h>

#define TOK   (4*4096)   // 16384 tokens
#define DMODEL 512
#define MLPD   2048
#define NH     8
#define DH     64
#define BS     128
#define NBLK   32        // 4096 / 128

// ---------------- scratch (no allocations allowed) ----------------
__device__ float g_xin[TOK*DMODEL];
__device__ float g_q  [TOK*DMODEL];
__device__ float g_k  [TOK*DMODEL];
__device__ float g_v  [TOK*DMODEL];
__device__ float g_ctx[TOK*DMODEL];
__device__ float g_x  [TOK*DMODEL];
__device__ float g_y  [TOK*DMODEL];
__device__ float g_h  [TOK*MLPD];

// ---------------- LayerNorm: one warp per token ----------------
__global__ void ln_kernel(const float* __restrict__ x,
                          const float* __restrict__ scale,
                          const float* __restrict__ bias,
                          float* __restrict__ out)
{
    int warp = (blockIdx.x * blockDim.x + threadIdx.x) >> 5;
    int lane = threadIdx.x & 31;
    if (warp >= TOK) return;
    const float* row = x + (size_t)warp * DMODEL;

    float4 v[4];
    float sum = 0.f;
#pragma unroll
    for (int i = 0; i < 4; i++) {
        v[i] = *(const float4*)&row[lane*4 + i*128];
        sum += v[i].x + v[i].y + v[i].z + v[i].w;
    }
#pragma unroll
    for (int o = 16; o; o >>= 1) sum += __shfl_xor_sync(0xffffffffu, sum, o);
    float mu = sum * (1.0f / DMODEL);

    float var = 0.f;
#pragma unroll
    for (int i = 0; i < 4; i++) {
        float dx = v[i].x - mu, dy = v[i].y - mu, dz = v[i].z - mu, dw = v[i].w - mu;
        var += dx*dx + dy*dy + dz*dz + dw*dw;
    }
#pragma unroll
    for (int o = 16; o; o >>= 1) var += __shfl_xor_sync(0xffffffffu, var, o);
    float rstd = rsqrtf(var * (1.0f / DMODEL) + 1e-6f);

    float* orow = out + (size_t)warp * DMODEL;
#pragma unroll
    for (int i = 0; i < 4; i++) {
        int c = lane*4 + i*128;
        float4 sc = *(const float4*)&scale[c];
        float4 bi = *(const float4*)&bias[c];
        float4 o4;
        o4.x = (v[i].x - mu) * rstd * sc.x + bi.x;
        o4.y = (v[i].y - mu) * rstd * sc.y + bi.y;
        o4.z = (v[i].z - mu) * rstd * sc.z + bi.z;
        o4.w = (v[i].w - mu) * rstd * sc.w + bi.w;
        *(float4*)&orow[c] = o4;
    }
}

// ---------------- GELU (tanh approx, matches jax.nn.gelu default) ----------------
__device__ __forceinline__ float gelu_f(float x)
{
    float x3 = x * x * x;
    return 0.5f * x * (1.0f + tanhf(0.7978845608028654f * (x + 0.044715f * x3)));
}

// ---------------- fp32 SGEMM: C[M,N] = A[M,K] * B[K,N] (+bias, gelu, +res) ----------------
// 128x128 tile, BK=8, 256 threads, 8x8 microtile, register prefetch.
template<int BIAS, int GELU, int RES>
__global__ __launch_bounds__(256, 2)
void gemm_kernel(const float* __restrict__ A, const float* __restrict__ B,
                 const float* __restrict__ bias, const float* __restrict__ res,
                 float* __restrict__ C, int M, int N, int K)
{
    __shared__ float As[8][128];
    __shared__ float Bs[8][132];   // padded row, 16B-aligned rows (132 % 4 == 0)

    int n0 = blockIdx.x * 128;
    int m0 = blockIdx.y * 128;
    int tid = threadIdx.x;

    int arow = tid >> 1;            // 0..127
    int acol = (tid & 1) * 4;       // 0 or 4
    int brow = tid >> 5;            // 0..7
    int bcol = (tid & 31) * 4;      // 0..124

    int tx = tid & 15;              // n microtile
    int ty = tid >> 4;              // m microtile

    float acc[8][8];
#pragma unroll
    for (int i = 0; i < 8; i++)
#pragma unroll
        for (int j = 0; j < 8; j++) acc[i][j] = 0.f;

    const float* Aptr = A + (size_t)(m0 + arow) * K + acol;
    float4 apre = *(const float4*)Aptr;
    float4 bpre = *(const float4*)&B[(size_t)brow * N + n0 + bcol];

    for (int k0 = 0; k0 < K; k0 += 8) {
        As[acol + 0][arow] = apre.x;
        As[acol + 1][arow] = apre.y;
        As[acol + 2][arow] = apre.z;
        As[acol + 3][arow] = apre.w;
        *(float4*)&Bs[brow][bcol] = bpre;
        __syncthreads();

        if (k0 + 8 < K) {
            apre = *(const float4*)(Aptr + k0 + 8);
            bpre = *(const float4*)&B[(size_t)(k0 + 8 + brow) * N + n0 + bcol];
        }

#pragma unroll
        for (int kk = 0; kk < 8; kk++) {
            float ar[8], br[8];
            *(float4*)&ar[0] = *(float4*)&As[kk][ty * 8];
            *(float4*)&ar[4] = *(float4*)&As[kk][ty * 8 + 4];
            *(float4*)&br[0] = *(float4*)&Bs[kk][tx * 8];
            *(float4*)&br[4] = *(float4*)&Bs[kk][tx * 8 + 4];
#pragma unroll
            for (int i = 0; i < 8; i++)
#pragma unroll
                for (int j = 0; j < 8; j++)
                    acc[i][j] = fmaf(ar[i], br[j], acc[i][j]);
        }
        __syncthreads();
    }

    // epilogue
#pragma unroll
    for (int i = 0; i < 8; i++) {
        int row = m0 + ty * 8 + i;
        int col = n0 + tx * 8;
        size_t base = (size_t)row * N + col;
        float o[8];
#pragma unroll
        for (int j = 0; j < 8; j++) {
            float val = acc[i][j];
            if (BIAS) val += bias[col + j];
            if (GELU) val = gelu_f(val);
            if (RES)  val += res[base + j];
            o[j] = val;
        }
        *(float4*)&C[base + 0] = *(float4*)&o[0];
        *(float4*)&C[base + 4] = *(float4*)&o[4];
    }
}

// ---------------- block-local attention: one CTA per (batch, block, head) ----------------
// smem: K tile 128x64 f32, V tile 128x64 f32, scores 128x129 f32  -> 131584 B dynamic
#define ATTN_SMEM ((BS*DH + BS*DH + BS*(BS+1)) * sizeof(float))

__global__ void attn_kernel(const float* __restrict__ q,
                            const float* __restrict__ k,
                            const float* __restrict__ v,
                            float* __restrict__ ctx)
{
    extern __shared__ float sm[];
    float* kb = sm;                 // [128][64]
    float* vb = kb + BS * DH;       // [128][64]
    float* sb = vb + BS * DH;       // [128][129]

    int bid = blockIdx.x;           // 1024 = 4 * 32 * 8
    int h   = bid & 7;
    int blk = (bid >> 3) & 31;
    int b   = bid >> 8;
    int t0  = b * 4096 + blk * BS;
    int c0  = h * DH;
    int tid = threadIdx.x;          // 128, one q row per thread

    // cooperative K/V load (2048 float4 each)
#pragma unroll
    for (int it = 0; it < 16; it++) {
        int idx = tid + it * 128;
        int row = idx >> 4;
        int d4  = (idx & 15) << 2;
        *(float4*)&kb[row * DH + d4] = *(const float4*)&k[(size_t)(t0 + row) * DMODEL + c0 + d4];
        *(float4*)&vb[row * DH + d4] = *(const float4*)&v[(size_t)(t0 + row) * DMODEL + c0 + d4];
    }

    // own q row (pre-scaled by DH^-0.5 = 1/8)
    float qr[DH];
    {
        const float* qrow = &q[(size_t)(t0 + tid) * DMODEL + c0];
#pragma unroll
        for (int i = 0; i < 16; i++) {
            float4 t4 = *(const float4*)&qrow[i * 4];
            qr[i*4+0] = t4.x * 0.125f;
            qr[i*4+1] = t4.y * 0.125f;
            qr[i*4+2] = t4.z * 0.125f;
            qr[i*4+3] = t4.w * 0.125f;
        }
    }
    __syncthreads();

    float* srow = &sb[tid * (BS + 1)];   // (tid + j) % 32 banks: conflict-free
    float maxv = -1e30f;
    for (int j = 0; j < BS; j++) {
        const float* kr = &kb[j * DH];
        float s = 0.f;
#pragma unroll
        for (int i = 0; i < 16; i++) {
            float4 k4 = *(const float4*)&kr[i * 4];
            s = fmaf(qr[i*4+0], k4.x, s);
            s = fmaf(qr[i*4+1], k4.y, s);
            s = fmaf(qr[i*4+2], k4.z, s);
            s = fmaf(qr[i*4+3], k4.w, s);
        }
        srow[j] = s;
        maxv = fmaxf(maxv, s);
    }

    float sum = 0.f;
    for (int j = 0; j < BS; j++) {
        float e = __expf(srow[j] - maxv);
        srow[j] = e;
        sum += e;
    }
    float inv = 1.0f / sum;

    float acc[DH];
#pragma unroll
    for (int i = 0; i < DH; i++) acc[i] = 0.f;
    for (int j = 0; j < BS; j++) {
        float p = srow[j];
        const float* vr = &vb[j * DH];
#pragma unroll
        for (int i = 0; i < 16; i++) {
            float4 v4 = *(const float4*)&vr[i * 4];
            acc[i*4+0] = fmaf(p, v4.x, acc[i*4+0]);
            acc[i*4+1] = fmaf(p, v4.y, acc[i*4+1]);
            acc[i*4+2] = fmaf(p, v4.z, acc[i*4+2]);
            acc[i*4+3] = fmaf(p, v4.w, acc[i*4+3]);
        }
    }

    float* orow = &ctx[(size_t)(t0 + tid) * DMODEL + c0];
#pragma unroll
    for (int i = 0; i < 16; i++) {
        float4 o4;
        o4.x = acc[i*4+0] * inv;
        o4.y = acc[i*4+1] * inv;
        o4.z = acc[i*4+2] * inv;
        o4.w = acc[i*4+3] * inv;
        *(float4*)&orow[i * 4] = o4;
    }
}

// ---------------- launch ----------------
extern "C" void kernel_launch(void* const* d_in, const int* in_sizes, int n_in,
                              void* d_out, int out_size)
{
    const float* inputs = (const float*)d_in[0];
    const float* ln1_s  = (const float*)d_in[1];
    const float* ln1_b  = (const float*)d_in[2];
    const float* wq     = (const float*)d_in[3];
    const float* wk     = (const float*)d_in[4];
    const float* wv     = (const float*)d_in[5];
    const float* wo     = (const float*)d_in[6];
    const float* ln2_s  = (const float*)d_in[7];
    const float* ln2_b  = (const float*)d_in[8];
    const float* w1     = (const float*)d_in[9];
    const float* b1     = (const float*)d_in[10];
    const float* w2     = (const float*)d_in[11];
    const float* b2     = (const float*)d_in[12];
    float* out = (float*)d_out;

    float *xin, *qb, *kb, *vb, *ctx, *xb, *yb, *hb;
    cudaGetSymbolAddress((void**)&xin, g_xin);
    cudaGetSymbolAddress((void**)&qb,  g_q);
    cudaGetSymbolAddress((void**)&kb,  g_k);
    cudaGetSymbolAddress((void**)&vb,  g_v);
    cudaGetSymbolAddress((void**)&ctx, g_ctx);
    cudaGetSymbolAddress((void**)&xb,  g_x);
    cudaGetSymbolAddress((void**)&yb,  g_y);
    cudaGetSymbolAddress((void**)&hb,  g_h);

    cudaFuncSetAttribute(attn_kernel, cudaFuncAttributeMaxDynamicSharedMemorySize,
                         (int)ATTN_SMEM);

    // 1. LN1
    ln_kernel<<<TOK / 8, 256>>>(inputs, ln1_s, ln1_b, xin);

    // 2. QKV projections
    dim3 gd(DMODEL / 128, TOK / 128);
    gemm_kernel<0,0,0><<<gd, 256>>>(xin, wq, nullptr, nullptr, qb, TOK, DMODEL, DMODEL);
    gemm_kernel<0,0,0><<<gd, 256>>>(xin, wk, nullptr, nullptr, kb, TOK, DMODEL, DMODEL);
    gemm_kernel<0,0,0><<<gd, 256>>>(xin, wv, nullptr, nullptr, vb, TOK, DMODEL, DMODEL);

    // 3. block-local attention
    attn_kernel<<<4 * NBLK * NH, 128, ATTN_SMEM>>>(qb, kb, vb, ctx);

    // 4. O projection + residual -> x
    gemm_kernel<0,0,1><<<gd, 256>>>(ctx, wo, nullptr, inputs, xb, TOK, DMODEL, DMODEL);

    // 5. LN2
    ln_kernel<<<TOK / 8, 256>>>(xb, ln2_s, ln2_b, yb);

    // 6. MLP up + gelu
    dim3 gm(MLPD / 128, TOK / 128);
    gemm_kernel<1,1,0><<<gm, 256>>>(yb, w1, b1, nullptr, hb, TOK, MLPD, DMODEL);

    // 7. MLP down + bias + residual -> out
    gemm_kernel<1,0,1><<<gd, 256>>>(hb, w2, b2, xb, out, TOK, DMODEL, MLPD);
}

// round 3
// speedup vs baseline: 1.8401x; 1.8401x over previous
#include <cuda_runtime.h>
#include <cuda_bf16.h>
#include <math.h>
#include <stdint.h>

#define TOK   (4*4096)
#define DMODEL 512
#define MLPD   2048
#define NH     8
#define DH     64
#define BS     128
#define NBLK   32

// ================= scratch =================
__device__ __nv_bfloat16 g_xin_hi[TOK*DMODEL];
__device__ __nv_bfloat16 g_xin_lo[TOK*DMODEL];
__device__ float g_q  [TOK*DMODEL];
__device__ float g_k  [TOK*DMODEL];
__device__ float g_v  [TOK*DMODEL];
__device__ __nv_bfloat16 g_ctx_hi[TOK*DMODEL];
__device__ __nv_bfloat16 g_ctx_lo[TOK*DMODEL];
__device__ float g_x  [TOK*DMODEL];
__device__ __nv_bfloat16 g_y_hi[TOK*DMODEL];
__device__ __nv_bfloat16 g_y_lo[TOK*DMODEL];
__device__ __nv_bfloat16 g_h_hi[TOK*MLPD];
__device__ __nv_bfloat16 g_h_lo[TOK*MLPD];
// split weights, native [K,N] layout
__device__ __nv_bfloat16 g_wq_hi[DMODEL*DMODEL], g_wq_lo[DMODEL*DMODEL];
__device__ __nv_bfloat16 g_wk_hi[DMODEL*DMODEL], g_wk_lo[DMODEL*DMODEL];
__device__ __nv_bfloat16 g_wv_hi[DMODEL*DMODEL], g_wv_lo[DMODEL*DMODEL];
__device__ __nv_bfloat16 g_wo_hi[DMODEL*DMODEL], g_wo_lo[DMODEL*DMODEL];
__device__ __nv_bfloat16 g_w1_hi[DMODEL*MLPD],   g_w1_lo[DMODEL*MLPD];
__device__ __nv_bfloat16 g_w2_hi[MLPD*DMODEL],   g_w2_lo[MLPD*DMODEL];

// ================= small helpers =================
__device__ __forceinline__ uint32_t smem_cast(const void* p) {
    return (uint32_t)__cvta_generic_to_shared(p);
}
__device__ __forceinline__ void cp16(uint32_t s, const void* g) {
    asm volatile("cp.async.cg.shared.global [%0], [%1], 16;" :: "r"(s), "l"(g));
}
#define CP_COMMIT() asm volatile("cp.async.commit_group;")
#define CP_WAIT(n)  asm volatile("cp.async.wait_group %0;" :: "n"(n))

__device__ __forceinline__ void ldsm4(uint32_t* r, uint32_t a) {
    asm volatile("ldmatrix.sync.aligned.m8n8.x4.shared.b16 {%0,%1,%2,%3}, [%4];"
                 : "=r"(r[0]), "=r"(r[1]), "=r"(r[2]), "=r"(r[3]) : "r"(a));
}
__device__ __forceinline__ void ldsm4t(uint32_t* r, uint32_t a) {
    asm volatile("ldmatrix.sync.aligned.m8n8.x4.trans.shared.b16 {%0,%1,%2,%3}, [%4];"
                 : "=r"(r[0]), "=r"(r[1]), "=r"(r[2]), "=r"(r[3]) : "r"(a));
}
__device__ __forceinline__ void mma16816(float* d, const uint32_t* a, const uint32_t* b) {
    asm volatile("mma.sync.aligned.m16n8k16.row.col.f32.bf16.bf16.f32 "
                 "{%0,%1,%2,%3},{%4,%5,%6,%7},{%8,%9},{%0,%1,%2,%3};"
                 : "+f"(d[0]), "+f"(d[1]), "+f"(d[2]), "+f"(d[3])
                 : "r"(a[0]), "r"(a[1]), "r"(a[2]), "r"(a[3]), "r"(b[0]), "r"(b[1]));
}

__device__ __forceinline__ float gelu_f(float x) {
    float x3 = x * x * x;
    return 0.5f * x * (1.0f + tanhf(0.7978845608028654f * (x + 0.044715f * x3)));
}
__device__ __forceinline__ void split_bf16(float v, __nv_bfloat16& hi, __nv_bfloat16& lo) {
    hi = __float2bfloat16(v);
    lo = __float2bfloat16(v - __bfloat162float(hi));
}

// ================= weight split (elementwise, keeps [K,N] layout) =================
__global__ void split_kernel(const float* __restrict__ w,
                             __nv_bfloat16* __restrict__ hi,
                             __nv_bfloat16* __restrict__ lo, int n)
{
    int i = (blockIdx.x * 256 + threadIdx.x) * 4;
    if (i >= n) return;
    float4 v = *(const float4*)&w[i];
    __nv_bfloat16 h0,l0,h1,l1,h2,l2,h3,l3;
    split_bf16(v.x,h0,l0); split_bf16(v.y,h1,l1);
    split_bf16(v.z,h2,l2); split_bf16(v.w,h3,l3);
    __nv_bfloat162 hh0 = {h0,h1}, hh1 = {h2,h3}, ll0 = {l0,l1}, ll1 = {l2,l3};
    *(__nv_bfloat162*)&hi[i]   = hh0; *(__nv_bfloat162*)&hi[i+2] = hh1;
    *(__nv_bfloat162*)&lo[i]   = ll0; *(__nv_bfloat162*)&lo[i+2] = ll1;
}

// ================= LayerNorm -> split bf16 =================
__global__ void ln_split_kernel(const float* __restrict__ x,
                                const float* __restrict__ scale,
                                const float* __restrict__ bias,
                                __nv_bfloat16* __restrict__ ohi,
                                __nv_bfloat16* __restrict__ olo)
{
    int warp = (blockIdx.x * blockDim.x + threadIdx.x) >> 5;
    int lane = threadIdx.x & 31;
    if (warp >= TOK) return;
    const float* row = x + (size_t)warp * DMODEL;

    float4 v[4];
    float sum = 0.f;
#pragma unroll
    for (int i = 0; i < 4; i++) {
        v[i] = *(const float4*)&row[lane*4 + i*128];
        sum += v[i].x + v[i].y + v[i].z + v[i].w;
    }
#pragma unroll
    for (int o = 16; o; o >>= 1) sum += __shfl_xor_sync(0xffffffffu, sum, o);
    float mu = sum * (1.0f / DMODEL);
    float var = 0.f;
#pragma unroll
    for (int i = 0; i < 4; i++) {
        float dx = v[i].x - mu, dy = v[i].y - mu, dz = v[i].z - mu, dw = v[i].w - mu;
        var += dx*dx + dy*dy + dz*dz + dw*dw;
    }
#pragma unroll
    for (int o = 16; o; o >>= 1) var += __shfl_xor_sync(0xffffffffu, var, o);
    float rstd = rsqrtf(var * (1.0f / DMODEL) + 1e-6f);

    size_t base = (size_t)warp * DMODEL;
#pragma unroll
    for (int i = 0; i < 4; i++) {
        int c = lane*4 + i*128;
        float4 sc = *(const float4*)&scale[c];
        float4 bi = *(const float4*)&bias[c];
        float o0 = (v[i].x - mu) * rstd * sc.x + bi.x;
        float o1 = (v[i].y - mu) * rstd * sc.y + bi.y;
        float o2 = (v[i].z - mu) * rstd * sc.z + bi.z;
        float o3 = (v[i].w - mu) * rstd * sc.w + bi.w;
        __nv_bfloat16 h0,l0,h1,l1,h2,l2,h3,l3;
        split_bf16(o0,h0,l0); split_bf16(o1,h1,l1);
        split_bf16(o2,h2,l2); split_bf16(o3,h3,l3);
        __nv_bfloat162 hh0 = {h0,h1}, hh1 = {h2,h3}, ll0 = {l0,l1}, ll1 = {l2,l3};
        *(__nv_bfloat162*)&ohi[base + c + 0] = hh0;
        *(__nv_bfloat162*)&ohi[base + c + 2] = hh1;
        *(__nv_bfloat162*)&olo[base + c + 0] = ll0;
        *(__nv_bfloat162*)&olo[base + c + 2] = ll1;
    }
}

// ================= HMMA bf16x3 GEMM =================
// C[M,N] = A[M,K]*B[K,N]; A hi/lo [M,K], B hi/lo [K,N] (native layout).
// Virtual 3K loop: phase 0 ahi*bhi, 1 ahi*blo, 2 alo*bhi. fp32 accum.
#define KT 32
#define GSTAGES 4
#define A_STRIDE 40            // bf16 elems per smem row (80B, conflict-free ldsm)
#define B_STRIDE 136           // (272B, conflict-free ldsm.trans)
#define A_BYTES (128 * A_STRIDE * 2)        // 10240
#define B_BYTES (KT * B_STRIDE * 2)         // 8704
#define STAGE_BYTES (A_BYTES + B_BYTES)     // 18944 (multiple of 128)
#define GEMM_SMEM (GSTAGES * STAGE_BYTES)   // 75776

template<int BIAS, int GELU, int RES, int SPLIT>
__global__ __launch_bounds__(256, 2)
void mma_gemm(const __nv_bfloat16* __restrict__ Ahi, const __nv_bfloat16* __restrict__ Alo,
              const __nv_bfloat16* __restrict__ Bhi, const __nv_bfloat16* __restrict__ Blo,
              const float* __restrict__ bias, const float* __restrict__ res,
              float* __restrict__ Cf,
              __nv_bfloat16* __restrict__ Chi, __nv_bfloat16* __restrict__ Clo,
              int N, int K)
{
    extern __shared__ char smembuf[];
    const uint32_t sbase = smem_cast(smembuf);
    const int tid = threadIdx.x, warp = tid >> 5, lane = tid & 31;
    const int m0 = blockIdx.y * 128, n0 = blockIdx.x * 128;
    const int nk = K / KT;
    const int T = 3 * nk;
    const int wm = (warp >> 1) * 32;      // warp m offset (4 warps in m)
    const int wn = (warp & 1) * 64;       // warp n offset (2 warps in n)

    float acc[2][8][4];
#pragma unroll
    for (int i = 0; i < 2; i++)
#pragma unroll
        for (int j = 0; j < 8; j++)
#pragma unroll
            for (int q = 0; q < 4; q++) acc[i][j][q] = 0.f;

    // per-thread stage-load geometry
    const int a_row0 = tid >> 1,           a_kc = (tid & 1) * 2;  // 2 chunks: kc and kc+1? no:
    // A: 512 chunks of 16B (128 rows x 4 chunks). thread handles chunks tid, tid+256.
    // B: 512 chunks (32 rows x 16 chunks). thread handles chunks tid, tid+256.

    auto issue = [&](int it) {
        int p  = (it >= 2 * nk) ? 2 : (it >= nk) ? 1 : 0;
        int kk = (it - p * nk) * KT;
        const __nv_bfloat16* Ag = (p < 2) ? Ahi : Alo;
        const __nv_bfloat16* Bg = (p == 1) ? Blo : Bhi;
        uint32_t sA = sbase + (uint32_t)(it % GSTAGES) * STAGE_BYTES;
        uint32_t sB = sA + A_BYTES;
#pragma unroll
        for (int c0 = 0; c0 < 2; c0++) {
            int c = tid + c0 * 256;
            int row = c >> 2, kc = c & 3;
            cp16(sA + row * (A_STRIDE * 2) + kc * 16,
                 Ag + (size_t)(m0 + row) * K + kk + kc * 8);
        }
#pragma unroll
        for (int c0 = 0; c0 < 2; c0++) {
            int c = tid + c0 * 256;
            int row = c >> 4, nc = c & 15;
            cp16(sB + row * (B_STRIDE * 2) + nc * 16,
                 Bg + (size_t)(kk + row) * N + n0 + nc * 8);
        }
        CP_COMMIT();
    };

#pragma unroll
    for (int s = 0; s < GSTAGES - 1; s++) issue(s);

    for (int it = 0; it < T; it++) {
        CP_WAIT(GSTAGES - 2);
        __syncthreads();
        if (it + GSTAGES - 1 < T) issue(it + GSTAGES - 1);

        uint32_t sA = sbase + (uint32_t)(it % GSTAGES) * STAGE_BYTES;
        uint32_t sB = sA + A_BYTES;
#pragma unroll
        for (int ks = 0; ks < 2; ks++) {
            uint32_t a[2][4];
#pragma unroll
            for (int mi = 0; mi < 2; mi++)
                ldsm4(a[mi], sA + ((wm + mi*16 + (lane & 15)) * A_STRIDE
                                   + ks*16 + (lane >> 4) * 8) * 2);
            uint32_t b[4][4];
#pragma unroll
            for (int bi = 0; bi < 4; bi++)
                ldsm4t(b[bi], sB + ((ks*16 + (lane & 15)) * B_STRIDE
                                    + wn + bi*16 + (lane >> 4) * 8) * 2);
#pragma unroll
            for (int mi = 0; mi < 2; mi++)
#pragma unroll
                for (int ni = 0; ni < 8; ni++)
                    mma16816(acc[mi][ni], a[mi], &b[ni >> 1][(ni & 1) * 2]);
        }
    }

    // epilogue: d-frag mapping row = lane/4 (+8), col = 2*(lane%4) (+1)
#pragma unroll
    for (int mi = 0; mi < 2; mi++) {
#pragma unroll
        for (int r = 0; r < 2; r++) {
            int row = m0 + wm + mi * 16 + r * 8 + (lane >> 2);
#pragma unroll
            for (int ni = 0; ni < 8; ni++) {
                int col = n0 + wn + ni * 8 + (lane & 3) * 2;
                size_t off = (size_t)row * N + col;
                float v0 = acc[mi][ni][r * 2 + 0];
                float v1 = acc[mi][ni][r * 2 + 1];
                if (BIAS) { v0 += bias[col]; v1 += bias[col + 1]; }
                if (GELU) { v0 = gelu_f(v0); v1 = gelu_f(v1); }
                if (RES)  { float2 rr = *(const float2*)&res[off]; v0 += rr.x; v1 += rr.y; }
                if (SPLIT) {
                    __nv_bfloat16 h0,l0,h1,l1;
                    split_bf16(v0,h0,l0); split_bf16(v1,h1,l1);
                    __nv_bfloat162 hh = {h0,h1}, ll = {l0,l1};
                    *(__nv_bfloat162*)&Chi[off] = hh;
                    *(__nv_bfloat162*)&Clo[off] = ll;
                } else {
                    float2 o = {v0, v1};
                    *(float2*)&Cf[off] = o;
                }
            }
        }
    }
}

// ================= block-local attention (fp32), split bf16 output =================
#define ATTN_SMEM ((BS*DH + BS*DH + BS*(BS+1)) * sizeof(float))

__global__ void attn_kernel(const float* __restrict__ q,
                            const float* __restrict__ k,
                            const float* __restrict__ v,
                            __nv_bfloat16* __restrict__ chi,
                            __nv_bfloat16* __restrict__ clo)
{
    extern __shared__ float sm[];
    float* kb = sm;
    float* vb = kb + BS * DH;
    float* sb = vb + BS * DH;

    int bid = blockIdx.x;
    int h   = bid & 7;
    int blk = (bid >> 3) & 31;
    int b   = bid >> 8;
    int t0  = b * 4096 + blk * BS;
    int c0  = h * DH;
    int tid = threadIdx.x;

#pragma unroll
    for (int it = 0; it < 16; it++) {
        int idx = tid + it * 128;
        int row = idx >> 4;
        int d4  = (idx & 15) << 2;
        *(float4*)&kb[row * DH + d4] = *(const float4*)&k[(size_t)(t0 + row) * DMODEL + c0 + d4];
        *(float4*)&vb[row * DH + d4] = *(const float4*)&v[(size_t)(t0 + row) * DMODEL + c0 + d4];
    }
    float qr[DH];
    {
        const float* qrow = &q[(size_t)(t0 + tid) * DMODEL + c0];
#pragma unroll
        for (int i = 0; i < 16; i++) {
            float4 t4 = *(const float4*)&qrow[i * 4];
            qr[i*4+0] = t4.x * 0.125f; qr[i*4+1] = t4.y * 0.125f;
            qr[i*4+2] = t4.z * 0.125f; qr[i*4+3] = t4.w * 0.125f;
        }
    }
    __syncthreads();

    float* srow = &sb[tid * (BS + 1)];
    float maxv = -1e30f;
    for (int j = 0; j < BS; j++) {
        const float* kr = &kb[j * DH];
        float s = 0.f;
#pragma unroll
        for (int i = 0; i < 16; i++) {
            float4 k4 = *(const float4*)&kr[i * 4];
            s = fmaf(qr[i*4+0], k4.x, s); s = fmaf(qr[i*4+1], k4.y, s);
            s = fmaf(qr[i*4+2], k4.z, s); s = fmaf(qr[i*4+3], k4.w, s);
        }
        srow[j] = s;
        maxv = fmaxf(maxv, s);
    }
    float sum = 0.f;
    for (int j = 0; j < BS; j++) {
        float e = __expf(srow[j] - maxv);
        srow[j] = e; sum += e;
    }
    float inv = 1.0f / sum;

    float acc[DH];
#pragma unroll
    for (int i = 0; i < DH; i++) acc[i] = 0.f;
    for (int j = 0; j < BS; j++) {
        float p = srow[j];
        const float* vr = &vb[j * DH];
#pragma unroll
        for (int i = 0; i < 16; i++) {
            float4 v4 = *(const float4*)&vr[i * 4];
            acc[i*4+0] = fmaf(p, v4.x, acc[i*4+0]); acc[i*4+1] = fmaf(p, v4.y, acc[i*4+1]);
            acc[i*4+2] = fmaf(p, v4.z, acc[i*4+2]); acc[i*4+3] = fmaf(p, v4.w, acc[i*4+3]);
        }
    }
    size_t obase = (size_t)(t0 + tid) * DMODEL + c0;
#pragma unroll
    for (int i = 0; i < DH; i += 2) {
        __nv_bfloat16 h0, l0, h1, l1;
        split_bf16(acc[i]   * inv, h0, l0);
        split_bf16(acc[i+1] * inv, h1, l1);
        __nv_bfloat162 hh = {h0, h1}, ll = {l0, l1};
        *(__nv_bfloat162*)&chi[obase + i] = hh;
        *(__nv_bfloat162*)&clo[obase + i] = ll;
    }
}

// ================= launch =================
extern "C" void kernel_launch(void* const* d_in, const int* in_sizes, int n_in,
                              void* d_out, int out_size)
{
    const float* inputs = (const float*)d_in[0];
    const float* ln1_s  = (const float*)d_in[1];
    const float* ln1_b  = (const float*)d_in[2];
    const float* wq     = (const float*)d_in[3];
    const float* wk     = (const float*)d_in[4];
    const float* wv     = (const float*)d_in[5];
    const float* wo     = (const float*)d_in[6];
    const float* ln2_s  = (const float*)d_in[7];
    const float* ln2_b  = (const float*)d_in[8];
    const float* w1     = (const float*)d_in[9];
    const float* b1     = (const float*)d_in[10];
    const float* w2     = (const float*)d_in[11];
    const float* b2     = (const float*)d_in[12];
    float* out = (float*)d_out;

    void *xin_hi, *xin_lo, *qb, *kb, *vb, *ctx_hi, *ctx_lo, *xb, *y_hi, *y_lo, *h_hi, *h_lo;
    void *wqh,*wql,*wkh,*wkl,*wvh,*wvl,*woh,*wol,*w1h,*w1l,*w2h,*w2l;
    cudaGetSymbolAddress(&xin_hi, g_xin_hi); cudaGetSymbolAddress(&xin_lo, g_xin_lo);
    cudaGetSymbolAddress(&qb, g_q); cudaGetSymbolAddress(&kb, g_k); cudaGetSymbolAddress(&vb, g_v);
    cudaGetSymbolAddress(&ctx_hi, g_ctx_hi); cudaGetSymbolAddress(&ctx_lo, g_ctx_lo);
    cudaGetSymbolAddress(&xb, g_x);
    cudaGetSymbolAddress(&y_hi, g_y_hi); cudaGetSymbolAddress(&y_lo, g_y_lo);
    cudaGetSymbolAddress(&h_hi, g_h_hi); cudaGetSymbolAddress(&h_lo, g_h_lo);
    cudaGetSymbolAddress(&wqh, g_wq_hi); cudaGetSymbolAddress(&wql, g_wq_lo);
    cudaGetSymbolAddress(&wkh, g_wk_hi); cudaGetSymbolAddress(&wkl, g_wk_lo);
    cudaGetSymbolAddress(&wvh, g_wv_hi); cudaGetSymbolAddress(&wvl, g_wv_lo);
    cudaGetSymbolAddress(&woh, g_wo_hi); cudaGetSymbolAddress(&wol, g_wo_lo);
    cudaGetSymbolAddress(&w1h, g_w1_hi); cudaGetSymbolAddress(&w1l, g_w1_lo);
    cudaGetSymbolAddress(&w2h, g_w2_hi); cudaGetSymbolAddress(&w2l, g_w2_lo);

    cudaFuncSetAttribute(mma_gemm<0,0,0,0>, cudaFuncAttributeMaxDynamicSharedMemorySize, GEMM_SMEM);
    cudaFuncSetAttribute(mma_gemm<0,0,1,0>, cudaFuncAttributeMaxDynamicSharedMemorySize, GEMM_SMEM);
    cudaFuncSetAttribute(mma_gemm<1,1,0,1>, cudaFuncAttributeMaxDynamicSharedMemorySize, GEMM_SMEM);
    cudaFuncSetAttribute(mma_gemm<1,0,1,0>, cudaFuncAttributeMaxDynamicSharedMemorySize, GEMM_SMEM);
    cudaFuncSetAttribute(attn_kernel, cudaFuncAttributeMaxDynamicSharedMemorySize, (int)ATTN_SMEM);

    // 0. weight splits (elementwise, no transpose)
    split_kernel<<<(DMODEL*DMODEL/4 + 255)/256, 256>>>(wq, (__nv_bfloat16*)wqh, (__nv_bfloat16*)wql, DMODEL*DMODEL);
    split_kernel<<<(DMODEL*DMODEL/4 + 255)/256, 256>>>(wk, (__nv_bfloat16*)wkh, (__nv_bfloat16*)wkl, DMODEL*DMODEL);
    split_kernel<<<(DMODEL*DMODEL/4 + 255)/256, 256>>>(wv, (__nv_bfloat16*)wvh, (__nv_bfloat16*)wvl, DMODEL*DMODEL);
    split_kernel<<<(DMODEL*DMODEL/4 + 255)/256, 256>>>(wo, (__nv_bfloat16*)woh, (__nv_bfloat16*)wol, DMODEL*DMODEL);
    split_kernel<<<(DMODEL*MLPD/4  + 255)/256, 256>>>(w1, (__nv_bfloat16*)w1h, (__nv_bfloat16*)w1l, DMODEL*MLPD);
    split_kernel<<<(DMODEL*MLPD/4  + 255)/256, 256>>>(w2, (__nv_bfloat16*)w2h, (__nv_bfloat16*)w2l, DMODEL*MLPD);

    // 1. LN1 -> split
    ln_split_kernel<<<TOK/8, 256>>>(inputs, ln1_s, ln1_b, (__nv_bfloat16*)xin_hi, (__nv_bfloat16*)xin_lo);

    // 2. QKV  (M=TOK, N=512, K=512)
    dim3 gd(DMODEL/128, TOK/128);
    mma_gemm<0,0,0,0><<<gd, 256, GEMM_SMEM>>>((__nv_bfloat16*)xin_hi, (__nv_bfloat16*)xin_lo,
        (__nv_bfloat16*)wqh, (__nv_bfloat16*)wql, nullptr, nullptr, (float*)qb, nullptr, nullptr, DMODEL, DMODEL);
    mma_gemm<0,0,0,0><<<gd, 256, GEMM_SMEM>>>((__nv_bfloat16*)xin_hi, (__nv_bfloat16*)xin_lo,
        (__nv_bfloat16*)wkh, (__nv_bfloat16*)wkl, nullptr, nullptr, (float*)kb, nullptr, nullptr, DMODEL, DMODEL);
    mma_gemm<0,0,0,0><<<gd, 256, GEMM_SMEM>>>((__nv_bfloat16*)xin_hi, (__nv_bfloat16*)xin_lo,
        (__nv_bfloat16*)wvh, (__nv_bfloat16*)wvl, nullptr, nullptr, (float*)vb, nullptr, nullptr, DMODEL, DMODEL);

    // 3. attention
    attn_kernel<<<4 * NBLK * NH, 128, ATTN_SMEM>>>((const float*)qb, (const float*)kb, (const float*)vb,
                                                   (__nv_bfloat16*)ctx_hi, (__nv_bfloat16*)ctx_lo);

    // 4. O proj + residual -> x
    mma_gemm<0,0,1,0><<<gd, 256, GEMM_SMEM>>>((__nv_bfloat16*)ctx_hi, (__nv_bfloat16*)ctx_lo,
        (__nv_bfloat16*)woh, (__nv_bfloat16*)wol, nullptr, inputs, (float*)xb, nullptr, nullptr, DMODEL, DMODEL);

    // 5. LN2 -> split
    ln_split_kernel<<<TOK/8, 256>>>((const float*)xb, ln2_s, ln2_b, (__nv_bfloat16*)y_hi, (__nv_bfloat16*)y_lo);

    // 6. MLP up + bias + gelu -> split h  (N=2048, K=512)
    dim3 gm(MLPD/128, TOK/128);
    mma_gemm<1,1,0,1><<<gm, 256, GEMM_SMEM>>>((__nv_bfloat16*)y_hi, (__nv_bfloat16*)y_lo,
        (__nv_bfloat16*)w1h, (__nv_bfloat16*)w1l, b1, nullptr, nullptr,
        (__nv_bfloat16*)h_hi, (__nv_bfloat16*)h_lo, MLPD, DMODEL);

    // 7. MLP down + bias + residual -> out  (N=512, K=2048)
    mma_gemm<1,0,1,0><<<gd, 256, GEMM_SMEM>>>((__nv_bfloat16*)h_hi, (__nv_bfloat16*)h_lo,
        (__nv_bfloat16*)w2h, (__nv_bfloat16*)w2l, b2, (const float*)xb, out, nullptr, nullptr, DMODEL, MLPD);
}

// round 4
// speedup vs baseline: 2.0869x; 1.1341x over previous
#include <cuda_runtime.h>
#include <cuda_bf16.h>
#include <math.h>
#include <stdint.h>

#define TOK   (4*4096)
#define DMODEL 512
#define MLPD   2048
#define NH     8
#define DH     64
#define BS     128
#define NBLK   32

// ================= scratch =================
__device__ __nv_bfloat16 g_xin_hi[TOK*DMODEL];
__device__ __nv_bfloat16 g_xin_lo[TOK*DMODEL];
__device__ float g_q  [TOK*DMODEL];
__device__ float g_k  [TOK*DMODEL];
__device__ float g_v  [TOK*DMODEL];
__device__ __nv_bfloat16 g_ctx_hi[TOK*DMODEL];
__device__ __nv_bfloat16 g_ctx_lo[TOK*DMODEL];
__device__ float g_x  [TOK*DMODEL];
__device__ __nv_bfloat16 g_y_hi[TOK*DMODEL];
__device__ __nv_bfloat16 g_y_lo[TOK*DMODEL];
__device__ __nv_bfloat16 g_h_hi[TOK*MLPD];
__device__ __nv_bfloat16 g_h_lo[TOK*MLPD];
// split weights, native [K,N] layout
__device__ __nv_bfloat16 g_wq_hi[DMODEL*DMODEL], g_wq_lo[DMODEL*DMODEL];
__device__ __nv_bfloat16 g_wk_hi[DMODEL*DMODEL], g_wk_lo[DMODEL*DMODEL];
__device__ __nv_bfloat16 g_wv_hi[DMODEL*DMODEL], g_wv_lo[DMODEL*DMODEL];
__device__ __nv_bfloat16 g_wo_hi[DMODEL*DMODEL], g_wo_lo[DMODEL*DMODEL];
__device__ __nv_bfloat16 g_w1_hi[DMODEL*MLPD],   g_w1_lo[DMODEL*MLPD];
__device__ __nv_bfloat16 g_w2_hi[MLPD*DMODEL],   g_w2_lo[MLPD*DMODEL];

// ================= small helpers =================
__device__ __forceinline__ uint32_t smem_cast(const void* p) {
    return (uint32_t)__cvta_generic_to_shared(p);
}
__device__ __forceinline__ void cp16(uint32_t s, const void* g) {
    asm volatile("cp.async.cg.shared.global [%0], [%1], 16;" :: "r"(s), "l"(g));
}
#define CP_COMMIT() asm volatile("cp.async.commit_group;")
#define CP_WAIT(n)  asm volatile("cp.async.wait_group %0;" :: "n"(n))

__device__ __forceinline__ void ldsm4(uint32_t* r, uint32_t a) {
    asm volatile("ldmatrix.sync.aligned.m8n8.x4.shared.b16 {%0,%1,%2,%3}, [%4];"
                 : "=r"(r[0]), "=r"(r[1]), "=r"(r[2]), "=r"(r[3]) : "r"(a));
}
__device__ __forceinline__ void ldsm4t(uint32_t* r, uint32_t a) {
    asm volatile("ldmatrix.sync.aligned.m8n8.x4.trans.shared.b16 {%0,%1,%2,%3}, [%4];"
                 : "=r"(r[0]), "=r"(r[1]), "=r"(r[2]), "=r"(r[3]) : "r"(a));
}
__device__ __forceinline__ void mma16816(float* d, const uint32_t* a, const uint32_t* b) {
    asm volatile("mma.sync.aligned.m16n8k16.row.col.f32.bf16.bf16.f32 "
                 "{%0,%1,%2,%3},{%4,%5,%6,%7},{%8,%9},{%0,%1,%2,%3};"
                 : "+f"(d[0]), "+f"(d[1]), "+f"(d[2]), "+f"(d[3])
                 : "r"(a[0]), "r"(a[1]), "r"(a[2]), "r"(a[3]), "r"(b[0]), "r"(b[1]));
}

__device__ __forceinline__ float gelu_f(float x) {
    float x3 = x * x * x;
    return 0.5f * x * (1.0f + tanhf(0.7978845608028654f * (x + 0.044715f * x3)));
}
__device__ __forceinline__ void split_bf16(float v, __nv_bfloat16& hi, __nv_bfloat16& lo) {
    hi = __float2bfloat16(v);
    lo = __float2bfloat16(v - __bfloat162float(hi));
}

// ================= weight split (elementwise, keeps [K,N] layout) =================
__global__ void split_kernel(const float* __restrict__ w,
                             __nv_bfloat16* __restrict__ hi,
                             __nv_bfloat16* __restrict__ lo, int n)
{
    int i = (blockIdx.x * 256 + threadIdx.x) * 4;
    if (i >= n) return;
    float4 v = *(const float4*)&w[i];
    __nv_bfloat16 h0,l0,h1,l1,h2,l2,h3,l3;
    split_bf16(v.x,h0,l0); split_bf16(v.y,h1,l1);
    split_bf16(v.z,h2,l2); split_bf16(v.w,h3,l3);
    __nv_bfloat162 hh0 = {h0,h1}, hh1 = {h2,h3}, ll0 = {l0,l1}, ll1 = {l2,l3};
    *(__nv_bfloat162*)&hi[i]   = hh0; *(__nv_bfloat162*)&hi[i+2] = hh1;
    *(__nv_bfloat162*)&lo[i]   = ll0; *(__nv_bfloat162*)&lo[i+2] = ll1;
}

// ================= LayerNorm -> split bf16 =================
__global__ void ln_split_kernel(const float* __restrict__ x,
                                const float* __restrict__ scale,
                                const float* __restrict__ bias,
                                __nv_bfloat16* __restrict__ ohi,
                                __nv_bfloat16* __restrict__ olo)
{
    int warp = (blockIdx.x * blockDim.x + threadIdx.x) >> 5;
    int lane = threadIdx.x & 31;
    if (warp >= TOK) return;
    const float* row = x + (size_t)warp * DMODEL;

    float4 v[4];
    float sum = 0.f;
#pragma unroll
    for (int i = 0; i < 4; i++) {
        v[i] = *(const float4*)&row[lane*4 + i*128];
        sum += v[i].x + v[i].y + v[i].z + v[i].w;
    }
#pragma unroll
    for (int o = 16; o; o >>= 1) sum += __shfl_xor_sync(0xffffffffu, sum, o);
    float mu = sum * (1.0f / DMODEL);
    float var = 0.f;
#pragma unroll
    for (int i = 0; i < 4; i++) {
        float dx = v[i].x - mu, dy = v[i].y - mu, dz = v[i].z - mu, dw = v[i].w - mu;
        var += dx*dx + dy*dy + dz*dz + dw*dw;
    }
#pragma unroll
    for (int o = 16; o; o >>= 1) var += __shfl_xor_sync(0xffffffffu, var, o);
    float rstd = rsqrtf(var * (1.0f / DMODEL) + 1e-6f);

    size_t base = (size_t)warp * DMODEL;
#pragma unroll
    for (int i = 0; i < 4; i++) {
        int c = lane*4 + i*128;
        float4 sc = *(const float4*)&scale[c];
        float4 bi = *(const float4*)&bias[c];
        float o0 = (v[i].x - mu) * rstd * sc.x + bi.x;
        float o1 = (v[i].y - mu) * rstd * sc.y + bi.y;
        float o2 = (v[i].z - mu) * rstd * sc.z + bi.z;
        float o3 = (v[i].w - mu) * rstd * sc.w + bi.w;
        __nv_bfloat16 h0,l0,h1,l1,h2,l2,h3,l3;
        split_bf16(o0,h0,l0); split_bf16(o1,h1,l1);
        split_bf16(o2,h2,l2); split_bf16(o3,h3,l3);
        __nv_bfloat162 hh0 = {h0,h1}, hh1 = {h2,h3}, ll0 = {l0,l1}, ll1 = {l2,l3};
        *(__nv_bfloat162*)&ohi[base + c + 0] = hh0;
        *(__nv_bfloat162*)&ohi[base + c + 2] = hh1;
        *(__nv_bfloat162*)&olo[base + c + 0] = ll0;
        *(__nv_bfloat162*)&olo[base + c + 2] = ll1;
    }
}

// ================= HMMA bf16x3 GEMM (v2: 64x64 warp tile, frag double-buffer) =================
// C[M,N] = A[M,K]*B[K,N]; A hi/lo [M,K], B hi/lo [K,N].
// Virtual 3K loop: phase 0 ahi*bhi, 1 ahi*blo, 2 alo*bhi. fp32 accum.
// CTA: 128 threads, 4 warps in 2x2, warp tile 64x64, KT=32, 5-stage cp.async.
#define KT 32
#define GSTAGES 5
#define A_STRIDE 40            // bf16 elems per smem row (80B, conflict-free ldsm)
#define B_STRIDE 136           // (272B, conflict-free ldsm.trans)
#define A_BYTES (128 * A_STRIDE * 2)        // 10240
#define B_BYTES (KT * B_STRIDE * 2)         // 8704
#define STAGE_BYTES (A_BYTES + B_BYTES)     // 18944
#define GEMM_SMEM (GSTAGES * STAGE_BYTES)   // 94720

template<int BIAS, int GELU, int RES, int SPLIT>
__global__ __launch_bounds__(128, 2)
void mma_gemm(const __nv_bfloat16* __restrict__ Ahi, const __nv_bfloat16* __restrict__ Alo,
              const __nv_bfloat16* __restrict__ Bhi, const __nv_bfloat16* __restrict__ Blo,
              const float* __restrict__ bias, const float* __restrict__ res,
              float* __restrict__ Cf,
              __nv_bfloat16* __restrict__ Chi, __nv_bfloat16* __restrict__ Clo,
              int N, int K)
{
    extern __shared__ char smembuf[];
    const uint32_t sbase = smem_cast(smembuf);
    const int tid = threadIdx.x, warp = tid >> 5, lane = tid & 31;
    const int m0 = blockIdx.y * 128, n0 = blockIdx.x * 128;
    const int nk = K / KT;
    const int T = 3 * nk;
    const int wm = (warp >> 1) * 64;      // 2 warps in m
    const int wn = (warp & 1) * 64;       // 2 warps in n

    float acc[4][8][4];
#pragma unroll
    for (int i = 0; i < 4; i++)
#pragma unroll
        for (int j = 0; j < 8; j++)
#pragma unroll
            for (int q = 0; q < 4; q++) acc[i][j][q] = 0.f;

    // per-thread load geometry: A 512 x 16B chunks, B 512 x 16B chunks, 4 each
    const int a_row = tid >> 2, a_kc = tid & 3;         // + q*32 rows
    const int b_row = tid >> 4, b_nc = tid & 15;        // + q*8 rows

    auto issue = [&](int it) {
        int p  = (it >= 2 * nk) ? 2 : (it >= nk) ? 1 : 0;
        int kk = (it - p * nk) * KT;
        const __nv_bfloat16* Ag = (p < 2) ? Ahi : Alo;
        const __nv_bfloat16* Bg = (p == 1) ? Blo : Bhi;
        uint32_t sA = sbase + (uint32_t)(it % GSTAGES) * STAGE_BYTES;
        uint32_t sB = sA + A_BYTES;
#pragma unroll
        for (int q = 0; q < 4; q++) {
            int row = a_row + q * 32;
            cp16(sA + row * (A_STRIDE * 2) + a_kc * 16,
                 Ag + (size_t)(m0 + row) * K + kk + a_kc * 8);
        }
#pragma unroll
        for (int q = 0; q < 4; q++) {
            int row = b_row + q * 8;
            cp16(sB + row * (B_STRIDE * 2) + b_nc * 16,
                 Bg + (size_t)(kk + row) * N + n0 + b_nc * 8);
        }
        CP_COMMIT();
    };

#pragma unroll
    for (int s = 0; s < GSTAGES - 1; s++) issue(s);

    // ldsm address components (byte offsets within stage)
    const uint32_t a_off = ((wm + (lane & 15)) * A_STRIDE + (lane >> 4) * 8) * 2;
    const uint32_t b_off = (((lane & 15)) * B_STRIDE + wn + (lane >> 4) * 8) * 2;

    uint32_t af[2][4][4], bf[2][4][4];

    for (int it = 0; it < T; it++) {
        CP_WAIT(3);
        __syncthreads();
        if (it + GSTAGES - 1 < T) issue(it + GSTAGES - 1);

        uint32_t sA = sbase + (uint32_t)(it % GSTAGES) * STAGE_BYTES;
        uint32_t sB = sA + A_BYTES;

        // load ks=0 frags
#pragma unroll
        for (int mi = 0; mi < 4; mi++)
            ldsm4(af[0][mi], sA + a_off + (mi * 16 * A_STRIDE) * 2);
#pragma unroll
        for (int bi = 0; bi < 4; bi++)
            ldsm4t(bf[0][bi], sB + b_off + (bi * 16) * 2);
        // prefetch ks=1 frags (independent; hidden under ks=0 MMAs)
#pragma unroll
        for (int mi = 0; mi < 4; mi++)
            ldsm4(af[1][mi], sA + a_off + (mi * 16 * A_STRIDE + 16) * 2);
#pragma unroll
        for (int bi = 0; bi < 4; bi++)
            ldsm4t(bf[1][bi], sB + b_off + (16 * B_STRIDE + bi * 16) * 2);

#pragma unroll
        for (int ks = 0; ks < 2; ks++)
#pragma unroll
            for (int mi = 0; mi < 4; mi++)
#pragma unroll
                for (int ni = 0; ni < 8; ni++)
                    mma16816(acc[mi][ni], af[ks][mi], &bf[ks][ni >> 1][(ni & 1) * 2]);
    }

    // epilogue
#pragma unroll
    for (int mi = 0; mi < 4; mi++) {
#pragma unroll
        for (int r = 0; r < 2; r++) {
            int row = m0 + wm + mi * 16 + r * 8 + (lane >> 2);
#pragma unroll
            for (int ni = 0; ni < 8; ni++) {
                int col = n0 + wn + ni * 8 + (lane & 3) * 2;
                size_t off = (size_t)row * N + col;
                float v0 = acc[mi][ni][r * 2 + 0];
                float v1 = acc[mi][ni][r * 2 + 1];
                if (BIAS) { v0 += bias[col]; v1 += bias[col + 1]; }
                if (GELU) { v0 = gelu_f(v0); v1 = gelu_f(v1); }
                if (RES)  { float2 rr = *(const float2*)&res[off]; v0 += rr.x; v1 += rr.y; }
                if (SPLIT) {
                    __nv_bfloat16 h0,l0,h1,l1;
                    split_bf16(v0,h0,l0); split_bf16(v1,h1,l1);
                    __nv_bfloat162 hh = {h0,h1}, ll = {l0,l1};
                    *(__nv_bfloat162*)&Chi[off] = hh;
                    *(__nv_bfloat162*)&Clo[off] = ll;
                } else {
                    float2 o = {v0, v1};
                    *(float2*)&Cf[off] = o;
                }
            }
        }
    }
}

// ================= block-local attention (fp32), split bf16 output =================
#define ATTN_SMEM ((BS*DH + BS*DH + BS*(BS+1)) * sizeof(float))

__global__ void attn_kernel(const float* __restrict__ q,
                            const float* __restrict__ k,
                            const float* __restrict__ v,
                            __nv_bfloat16* __restrict__ chi,
                            __nv_bfloat16* __restrict__ clo)
{
    extern __shared__ float sm[];
    float* kb = sm;
    float* vb = kb + BS * DH;
    float* sb = vb + BS * DH;

    int bid = blockIdx.x;
    int h   = bid & 7;
    int blk = (bid >> 3) & 31;
    int b   = bid >> 8;
    int t0  = b * 4096 + blk * BS;
    int c0  = h * DH;
    int tid = threadIdx.x;

#pragma unroll
    for (int it = 0; it < 16; it++) {
        int idx = tid + it * 128;
        int row = idx >> 4;
        int d4  = (idx & 15) << 2;
        *(float4*)&kb[row * DH + d4] = *(const float4*)&k[(size_t)(t0 + row) * DMODEL + c0 + d4];
        *(float4*)&vb[row * DH + d4] = *(const float4*)&v[(size_t)(t0 + row) * DMODEL + c0 + d4];
    }
    float qr[DH];
    {
        const float* qrow = &q[(size_t)(t0 + tid) * DMODEL + c0];
#pragma unroll
        for (int i = 0; i < 16; i++) {
            float4 t4 = *(const float4*)&qrow[i * 4];
            qr[i*4+0] = t4.x * 0.125f; qr[i*4+1] = t4.y * 0.125f;
            qr[i*4+2] = t4.z * 0.125f; qr[i*4+3] = t4.w * 0.125f;
        }
    }
    __syncthreads();

    float* srow = &sb[tid * (BS + 1)];
    float maxv = -1e30f;
    for (int j = 0; j < BS; j++) {
        const float* kr = &kb[j * DH];
        float s = 0.f;
#pragma unroll
        for (int i = 0; i < 16; i++) {
            float4 k4 = *(const float4*)&kr[i * 4];
            s = fmaf(qr[i*4+0], k4.x, s); s = fmaf(qr[i*4+1], k4.y, s);
            s = fmaf(qr[i*4+2], k4.z, s); s = fmaf(qr[i*4+3], k4.w, s);
        }
        srow[j] = s;
        maxv = fmaxf(maxv, s);
    }
    float sum = 0.f;
    for (int j = 0; j < BS; j++) {
        float e = __expf(srow[j] - maxv);
        srow[j] = e; sum += e;
    }
    float inv = 1.0f / sum;

    float acc[DH];
#pragma unroll
    for (int i = 0; i < DH; i++) acc[i] = 0.f;
    for (int j = 0; j < BS; j++) {
        float p = srow[j];
        const float* vr = &vb[j * DH];
#pragma unroll
        for (int i = 0; i < 16; i++) {
            float4 v4 = *(const float4*)&vr[i * 4];
            acc[i*4+0] = fmaf(p, v4.x, acc[i*4+0]); acc[i*4+1] = fmaf(p, v4.y, acc[i*4+1]);
            acc[i*4+2] = fmaf(p, v4.z, acc[i*4+2]); acc[i*4+3] = fmaf(p, v4.w, acc[i*4+3]);
        }
    }
    size_t obase = (size_t)(t0 + tid) * DMODEL + c0;
#pragma unroll
    for (int i = 0; i < DH; i += 2) {
        __nv_bfloat16 h0, l0, h1, l1;
        split_bf16(acc[i]   * inv, h0, l0);
        split_bf16(acc[i+1] * inv, h1, l1);
        __nv_bfloat162 hh = {h0, h1}, ll = {l0, l1};
        *(__nv_bfloat162*)&chi[obase + i] = hh;
        *(__nv_bfloat162*)&clo[obase + i] = ll;
    }
}

// ================= launch =================
extern "C" void kernel_launch(void* const* d_in, const int* in_sizes, int n_in,
                              void* d_out, int out_size)
{
    const float* inputs = (const float*)d_in[0];
    const float* ln1_s  = (const float*)d_in[1];
    const float* ln1_b  = (const float*)d_in[2];
    const float* wq     = (const float*)d_in[3];
    const float* wk     = (const float*)d_in[4];
    const float* wv     = (const float*)d_in[5];
    const float* wo     = (const float*)d_in[6];
    const float* ln2_s  = (const float*)d_in[7];
    const float* ln2_b  = (const float*)d_in[8];
    const float* w1     = (const float*)d_in[9];
    const float* b1     = (const float*)d_in[10];
    const float* w2     = (const float*)d_in[11];
    const float* b2     = (const float*)d_in[12];
    float* out = (float*)d_out;

    void *xin_hi, *xin_lo, *qb, *kb, *vb, *ctx_hi, *ctx_lo, *xb, *y_hi, *y_lo, *h_hi, *h_lo;
    void *wqh,*wql,*wkh,*wkl,*wvh,*wvl,*woh,*wol,*w1h,*w1l,*w2h,*w2l;
    cudaGetSymbolAddress(&xin_hi, g_xin_hi); cudaGetSymbolAddress(&xin_lo, g_xin_lo);
    cudaGetSymbolAddress(&qb, g_q); cudaGetSymbolAddress(&kb, g_k); cudaGetSymbolAddress(&vb, g_v);
    cudaGetSymbolAddress(&ctx_hi, g_ctx_hi); cudaGetSymbolAddress(&ctx_lo, g_ctx_lo);
    cudaGetSymbolAddress(&xb, g_x);
    cudaGetSymbolAddress(&y_hi, g_y_hi); cudaGetSymbolAddress(&y_lo, g_y_lo);
    cudaGetSymbolAddress(&h_hi, g_h_hi); cudaGetSymbolAddress(&h_lo, g_h_lo);
    cudaGetSymbolAddress(&wqh, g_wq_hi); cudaGetSymbolAddress(&wql, g_wq_lo);
    cudaGetSymbolAddress(&wkh, g_wk_hi); cudaGetSymbolAddress(&wkl, g_wk_lo);
    cudaGetSymbolAddress(&wvh, g_wv_hi); cudaGetSymbolAddress(&wvl, g_wv_lo);
    cudaGetSymbolAddress(&woh, g_wo_hi); cudaGetSymbolAddress(&wol, g_wo_lo);
    cudaGetSymbolAddress(&w1h, g_w1_hi); cudaGetSymbolAddress(&w1l, g_w1_lo);
    cudaGetSymbolAddress(&w2h, g_w2_hi); cudaGetSymbolAddress(&w2l, g_w2_lo);

    cudaFuncSetAttribute(mma_gemm<0,0,0,0>, cudaFuncAttributeMaxDynamicSharedMemorySize, GEMM_SMEM);
    cudaFuncSetAttribute(mma_gemm<0,0,1,0>, cudaFuncAttributeMaxDynamicSharedMemorySize, GEMM_SMEM);
    cudaFuncSetAttribute(mma_gemm<1,1,0,1>, cudaFuncAttributeMaxDynamicSharedMemorySize, GEMM_SMEM);
    cudaFuncSetAttribute(mma_gemm<1,0,1,0>, cudaFuncAttributeMaxDynamicSharedMemorySize, GEMM_SMEM);
    cudaFuncSetAttribute(attn_kernel, cudaFuncAttributeMaxDynamicSharedMemorySize, (int)ATTN_SMEM);

    // 0. weight splits
    split_kernel<<<(DMODEL*DMODEL/4 + 255)/256, 256>>>(wq, (__nv_bfloat16*)wqh, (__nv_bfloat16*)wql, DMODEL*DMODEL);
    split_kernel<<<(DMODEL*DMODEL/4 + 255)/256, 256>>>(wk, (__nv_bfloat16*)wkh, (__nv_bfloat16*)wkl, DMODEL*DMODEL);
    split_kernel<<<(DMODEL*DMODEL/4 + 255)/256, 256>>>(wv, (__nv_bfloat16*)wvh, (__nv_bfloat16*)wvl, DMODEL*DMODEL);
    split_kernel<<<(DMODEL*DMODEL/4 + 255)/256, 256>>>(wo, (__nv_bfloat16*)woh, (__nv_bfloat16*)wol, DMODEL*DMODEL);
    split_kernel<<<(DMODEL*MLPD/4  + 255)/256, 256>>>(w1, (__nv_bfloat16*)w1h, (__nv_bfloat16*)w1l, DMODEL*MLPD);
    split_kernel<<<(DMODEL*MLPD/4  + 255)/256, 256>>>(w2, (__nv_bfloat16*)w2h, (__nv_bfloat16*)w2l, DMODEL*MLPD);

    // 1. LN1 -> split
    ln_split_kernel<<<TOK/8, 256>>>(inputs, ln1_s, ln1_b, (__nv_bfloat16*)xin_hi, (__nv_bfloat16*)xin_lo);

    // 2. QKV  (M=TOK, N=512, K=512)
    dim3 gd(DMODEL/128, TOK/128);
    mma_gemm<0,0,0,0><<<gd, 128, GEMM_SMEM>>>((__nv_bfloat16*)xin_hi, (__nv_bfloat16*)xin_lo,
        (__nv_bfloat16*)wqh, (__nv_bfloat16*)wql, nullptr, nullptr, (float*)qb, nullptr, nullptr, DMODEL, DMODEL);
    mma_gemm<0,0,0,0><<<gd, 128, GEMM_SMEM>>>((__nv_bfloat16*)xin_hi, (__nv_bfloat16*)xin_lo,
        (__nv_bfloat16*)wkh, (__nv_bfloat16*)wkl, nullptr, nullptr, (float*)kb, nullptr, nullptr, DMODEL, DMODEL);
    mma_gemm<0,0,0,0><<<gd, 128, GEMM_SMEM>>>((__nv_bfloat16*)xin_hi, (__nv_bfloat16*)xin_lo,
        (__nv_bfloat16*)wvh, (__nv_bfloat16*)wvl, nullptr, nullptr, (float*)vb, nullptr, nullptr, DMODEL, DMODEL);

    // 3. attention
    attn_kernel<<<4 * NBLK * NH, 128, ATTN_SMEM>>>((const float*)qb, (const float*)kb, (const float*)vb,
                                                   (__nv_bfloat16*)ctx_hi, (__nv_bfloat16*)ctx_lo);

    // 4. O proj + residual -> x
    mma_gemm<0,0,1,0><<<gd, 128, GEMM_SMEM>>>((__nv_bfloat16*)ctx_hi, (__nv_bfloat16*)ctx_lo,
        (__nv_bfloat16*)woh, (__nv_bfloat16*)wol, nullptr, inputs, (float*)xb, nullptr, nullptr, DMODEL, DMODEL);

    // 5. LN2 -> split
    ln_split_kernel<<<TOK/8, 256>>>((const float*)xb, ln2_s, ln2_b, (__nv_bfloat16*)y_hi, (__nv_bfloat16*)y_lo);

    // 6. MLP up + bias + gelu -> split h  (N=2048, K=512)
    dim3 gm(MLPD/128, TOK/128);
    mma_gemm<1,1,0,1><<<gm, 128, GEMM_SMEM>>>((__nv_bfloat16*)y_hi, (__nv_bfloat16*)y_lo,
        (__nv_bfloat16*)w1h, (__nv_bfloat16*)w1l, b1, nullptr, nullptr,
        (__nv_bfloat16*)h_hi, (__nv_bfloat16*)h_lo, MLPD, DMODEL);

    // 7. MLP down + bias + residual -> out  (N=512, K=2048)
    mma_gemm<1,0,1,0><<<gd, 128, GEMM_SMEM>>>((__nv_bfloat16*)h_hi, (__nv_bfloat16*)h_lo,
        (__nv_bfloat16*)w2h, (__nv_bfloat16*)w2l, b2, (const float*)xb, out, nullptr, nullptr, DMODEL, MLPD);
}

// round 5
// speedup vs baseline: 2.6992x; 1.2934x over previous
#include <cuda_runtime.h>
#include <cuda_fp16.h>
#include <math.h>
#include <stdint.h>

#define TOK   (4*4096)
#define DMODEL 512
#define QKVN  1536
#define MLPD   2048
#define NH     8
#define DH     64
#define BS     128
#define NBLK   32

// ================= scratch =================
__device__ __half g_xin[TOK*DMODEL];          // LN1 out, fp16
__device__ float  g_qkv[TOK*QKVN];            // q|k|v fused, fp32
__device__ __half g_ctx[TOK*DMODEL];          // attention out, fp16
__device__ float  g_x  [TOK*DMODEL];          // attn + residual, fp32
__device__ __half g_y  [TOK*DMODEL];          // LN2 out, fp16
__device__ __half g_h  [TOK*MLPD];            // MLP hidden, fp16
// weights: fp16 hi/lo pairs, native [K,N] layout
__device__ __half g_wqkv_hi[DMODEL*QKVN], g_wqkv_lo[DMODEL*QKVN];
__device__ __half g_wo_hi[DMODEL*DMODEL], g_wo_lo[DMODEL*DMODEL];
__device__ __half g_w1_hi[DMODEL*MLPD],   g_w1_lo[DMODEL*MLPD];
__device__ __half g_w2_hi[MLPD*DMODEL],   g_w2_lo[MLPD*DMODEL];

// ================= small helpers =================
__device__ __forceinline__ uint32_t smem_cast(const void* p) {
    return (uint32_t)__cvta_generic_to_shared(p);
}
__device__ __forceinline__ void cp16(uint32_t s, const void* g) {
    asm volatile("cp.async.cg.shared.global [%0], [%1], 16;" :: "r"(s), "l"(g));
}
#define CP_COMMIT() asm volatile("cp.async.commit_group;")
#define CP_WAIT(n)  asm volatile("cp.async.wait_group %0;" :: "n"(n))

__device__ __forceinline__ void ldsm4(uint32_t* r, uint32_t a) {
    asm volatile("ldmatrix.sync.aligned.m8n8.x4.shared.b16 {%0,%1,%2,%3}, [%4];"
                 : "=r"(r[0]), "=r"(r[1]), "=r"(r[2]), "=r"(r[3]) : "r"(a));
}
__device__ __forceinline__ void ldsm4t(uint32_t* r, uint32_t a) {
    asm volatile("ldmatrix.sync.aligned.m8n8.x4.trans.shared.b16 {%0,%1,%2,%3}, [%4];"
                 : "=r"(r[0]), "=r"(r[1]), "=r"(r[2]), "=r"(r[3]) : "r"(a));
}
__device__ __forceinline__ void mma16816(float* d, const uint32_t* a, const uint32_t* b) {
    asm volatile("mma.sync.aligned.m16n8k16.row.col.f32.f16.f16.f32 "
                 "{%0,%1,%2,%3},{%4,%5,%6,%7},{%8,%9},{%0,%1,%2,%3};"
                 : "+f"(d[0]), "+f"(d[1]), "+f"(d[2]), "+f"(d[3])
                 : "r"(a[0]), "r"(a[1]), "r"(a[2]), "r"(a[3]), "r"(b[0]), "r"(b[1]));
}

__device__ __forceinline__ float gelu_f(float x) {
    float x3 = x * x * x;
    return 0.5f * x * (1.0f + tanhf(0.7978845608028654f * (x + 0.044715f * x3)));
}
__device__ __forceinline__ void wsplit_f16(float v, __half& hi, __half& lo) {
    hi = __float2half_rn(v);
    lo = __float2half_rn(v - __half2float(hi));
}

// ================= weight split kernels =================
// generic: w[K,N] f32 -> hi/lo [K,N] fp16 (contiguous)
__global__ void wsplit_kernel(const float* __restrict__ w,
                              __half* __restrict__ hi, __half* __restrict__ lo, int n)
{
    int i = (blockIdx.x * 256 + threadIdx.x) * 4;
    if (i >= n) return;
    float4 v = *(const float4*)&w[i];
    __half h0,l0,h1,l1,h2,l2,h3,l3;
    wsplit_f16(v.x,h0,l0); wsplit_f16(v.y,h1,l1);
    wsplit_f16(v.z,h2,l2); wsplit_f16(v.w,h3,l3);
    __half2 hh0 = {h0,h1}, hh1 = {h2,h3}, ll0 = {l0,l1}, ll1 = {l2,l3};
    *(__half2*)&hi[i]   = hh0; *(__half2*)&hi[i+2] = hh1;
    *(__half2*)&lo[i]   = ll0; *(__half2*)&lo[i+2] = ll1;
}

// qkv pack: w[512,512] f32 -> wqkv hi/lo [512,1536] at column offset
__global__ void wsplit_qkv_kernel(const float* __restrict__ w,
                                  __half* __restrict__ hi, __half* __restrict__ lo,
                                  int coff)
{
    int i = (blockIdx.x * 256 + threadIdx.x) * 4;   // over 512*512
    if (i >= DMODEL*DMODEL) return;
    int k = i / DMODEL, n = i % DMODEL;
    float4 v = *(const float4*)&w[i];
    __half h0,l0,h1,l1,h2,l2,h3,l3;
    wsplit_f16(v.x,h0,l0); wsplit_f16(v.y,h1,l1);
    wsplit_f16(v.z,h2,l2); wsplit_f16(v.w,h3,l3);
    size_t o = (size_t)k * QKVN + coff + n;
    __half2 hh0 = {h0,h1}, hh1 = {h2,h3}, ll0 = {l0,l1}, ll1 = {l2,l3};
    *(__half2*)&hi[o]   = hh0; *(__half2*)&hi[o+2] = hh1;
    *(__half2*)&lo[o]   = ll0; *(__half2*)&lo[o+2] = ll1;
}

// ================= LayerNorm -> fp16 =================
__global__ void ln_h_kernel(const float* __restrict__ x,
                            const float* __restrict__ scale,
                            const float* __restrict__ bias,
                            __half* __restrict__ out)
{
    int warp = (blockIdx.x * blockDim.x + threadIdx.x) >> 5;
    int lane = threadIdx.x & 31;
    if (warp >= TOK) return;
    const float* row = x + (size_t)warp * DMODEL;

    float4 v[4];
    float sum = 0.f;
#pragma unroll
    for (int i = 0; i < 4; i++) {
        v[i] = *(const float4*)&row[lane*4 + i*128];
        sum += v[i].x + v[i].y + v[i].z + v[i].w;
    }
#pragma unroll
    for (int o = 16; o; o >>= 1) sum += __shfl_xor_sync(0xffffffffu, sum, o);
    float mu = sum * (1.0f / DMODEL);
    float var = 0.f;
#pragma unroll
    for (int i = 0; i < 4; i++) {
        float dx = v[i].x - mu, dy = v[i].y - mu, dz = v[i].z - mu, dw = v[i].w - mu;
        var += dx*dx + dy*dy + dz*dz + dw*dw;
    }
#pragma unroll
    for (int o = 16; o; o >>= 1) var += __shfl_xor_sync(0xffffffffu, var, o);
    float rstd = rsqrtf(var * (1.0f / DMODEL) + 1e-6f);

    size_t base = (size_t)warp * DMODEL;
#pragma unroll
    for (int i = 0; i < 4; i++) {
        int c = lane*4 + i*128;
        float4 sc = *(const float4*)&scale[c];
        float4 bi = *(const float4*)&bias[c];
        float o0 = (v[i].x - mu) * rstd * sc.x + bi.x;
        float o1 = (v[i].y - mu) * rstd * sc.y + bi.y;
        float o2 = (v[i].z - mu) * rstd * sc.z + bi.z;
        float o3 = (v[i].w - mu) * rstd * sc.w + bi.w;
        __half2 p0 = {__float2half_rn(o0), __float2half_rn(o1)};
        __half2 p1 = {__float2half_rn(o2), __float2half_rn(o3)};
        *(__half2*)&out[base + c + 0] = p0;
        *(__half2*)&out[base + c + 2] = p1;
    }
}

// ================= HMMA fp16 2-pass GEMM =================
// C[M,Nc] = A[M,K] * (Bhi + Blo)[K,Nc];  A single fp16, B fp16 hi/lo.
// CTA 128 thr, 4 warps 2x2, warp tile 64x64, CTA tile 128x128, KT=32, 5 stages.
#define KT 32
#define GSTAGES 5
#define A_STRIDE 40
#define B_STRIDE 136
#define A_BYTES (128 * A_STRIDE * 2)
#define B_BYTES (KT * B_STRIDE * 2)
#define STAGE_BYTES (A_BYTES + B_BYTES)
#define GEMM_SMEM (GSTAGES * STAGE_BYTES)

template<int BIAS, int GELU, int RES, int HOUT>
__global__ __launch_bounds__(128, 2)
void mma_gemm(const __half* __restrict__ A,
              const __half* __restrict__ Bhi, const __half* __restrict__ Blo,
              const float* __restrict__ bias, const float* __restrict__ res,
              float* __restrict__ Cf, __half* __restrict__ Ch,
              int N, int K)
{
    extern __shared__ char smembuf[];
    const uint32_t sbase = smem_cast(smembuf);
    const int tid = threadIdx.x, warp = tid >> 5, lane = tid & 31;
    const int m0 = blockIdx.y * 128, n0 = blockIdx.x * 128;
    const int nk = K / KT;
    const int T = 2 * nk;
    const int wm = (warp >> 1) * 64;
    const int wn = (warp & 1) * 64;

    float acc[4][8][4];
#pragma unroll
    for (int i = 0; i < 4; i++)
#pragma unroll
        for (int j = 0; j < 8; j++)
#pragma unroll
            for (int q = 0; q < 4; q++) acc[i][j][q] = 0.f;

    const int a_row = tid >> 2, a_kc = tid & 3;
    const int b_row = tid >> 4, b_nc = tid & 15;

    auto issue = [&](int it) {
        int p  = (it >= nk) ? 1 : 0;
        int kk = (it - p * nk) * KT;
        const __half* Bg = p ? Blo : Bhi;
        uint32_t sA = sbase + (uint32_t)(it % GSTAGES) * STAGE_BYTES;
        uint32_t sB = sA + A_BYTES;
#pragma unroll
        for (int q = 0; q < 4; q++) {
            int row = a_row + q * 32;
            cp16(sA + row * (A_STRIDE * 2) + a_kc * 16,
                 A + (size_t)(m0 + row) * K + kk + a_kc * 8);
        }
#pragma unroll
        for (int q = 0; q < 4; q++) {
            int row = b_row + q * 8;
            cp16(sB + row * (B_STRIDE * 2) + b_nc * 16,
                 Bg + (size_t)(kk + row) * N + n0 + b_nc * 8);
        }
        CP_COMMIT();
    };

#pragma unroll
    for (int s = 0; s < GSTAGES - 1; s++) issue(s);

    const uint32_t a_off = ((wm + (lane & 15)) * A_STRIDE + (lane >> 4) * 8) * 2;
    const uint32_t b_off = (((lane & 15)) * B_STRIDE + wn + (lane >> 4) * 8) * 2;

    uint32_t af[2][4][4], bf[2][4][4];

    for (int it = 0; it < T; it++) {
        CP_WAIT(3);
        __syncthreads();
        if (it + GSTAGES - 1 < T) issue(it + GSTAGES - 1);

        uint32_t sA = sbase + (uint32_t)(it % GSTAGES) * STAGE_BYTES;
        uint32_t sB = sA + A_BYTES;

#pragma unroll
        for (int mi = 0; mi < 4; mi++)
            ldsm4(af[0][mi], sA + a_off + (mi * 16 * A_STRIDE) * 2);
#pragma unroll
        for (int bi = 0; bi < 4; bi++)
            ldsm4t(bf[0][bi], sB + b_off + (bi * 16) * 2);
#pragma unroll
        for (int mi = 0; mi < 4; mi++)
            ldsm4(af[1][mi], sA + a_off + (mi * 16 * A_STRIDE + 16) * 2);
#pragma unroll
        for (int bi = 0; bi < 4; bi++)
            ldsm4t(bf[1][bi], sB + b_off + (16 * B_STRIDE + bi * 16) * 2);

#pragma unroll
        for (int ks = 0; ks < 2; ks++)
#pragma unroll
            for (int mi = 0; mi < 4; mi++)
#pragma unroll
                for (int ni = 0; ni < 8; ni++)
                    mma16816(acc[mi][ni], af[ks][mi], &bf[ks][ni >> 1][(ni & 1) * 2]);
    }

    // epilogue
#pragma unroll
    for (int mi = 0; mi < 4; mi++) {
#pragma unroll
        for (int r = 0; r < 2; r++) {
            int row = m0 + wm + mi * 16 + r * 8 + (lane >> 2);
#pragma unroll
            for (int ni = 0; ni < 8; ni++) {
                int col = n0 + wn + ni * 8 + (lane & 3) * 2;
                size_t off = (size_t)row * N + col;
                float v0 = acc[mi][ni][r * 2 + 0];
                float v1 = acc[mi][ni][r * 2 + 1];
                if (BIAS) { v0 += bias[col]; v1 += bias[col + 1]; }
                if (GELU) { v0 = gelu_f(v0); v1 = gelu_f(v1); }
                if (RES)  { float2 rr = *(const float2*)&res[off]; v0 += rr.x; v1 += rr.y; }
                if (HOUT) {
                    __half2 hh = {__float2half_rn(v0), __float2half_rn(v1)};
                    *(__half2*)&Ch[off] = hh;
                } else {
                    float2 o = {v0, v1};
                    *(float2*)&Cf[off] = o;
                }
            }
        }
    }
}

// ================= block-local attention (fp32 in from fused qkv, fp16 out) =================
#define ATTN_SMEM ((BS*DH + BS*DH + BS*(BS+1)) * sizeof(float))

__global__ void attn_kernel(const float* __restrict__ qkv,
                            __half* __restrict__ ctx)
{
    extern __shared__ float sm[];
    float* kb = sm;
    float* vb = kb + BS * DH;
    float* sb = vb + BS * DH;

    int bid = blockIdx.x;
    int h   = bid & 7;
    int blk = (bid >> 3) & 31;
    int b   = bid >> 8;
    int t0  = b * 4096 + blk * BS;
    int c0  = h * DH;
    int tid = threadIdx.x;

#pragma unroll
    for (int it = 0; it < 16; it++) {
        int idx = tid + it * 128;
        int row = idx >> 4;
        int d4  = (idx & 15) << 2;
        size_t rbase = (size_t)(t0 + row) * QKVN;
        *(float4*)&kb[row * DH + d4] = *(const float4*)&qkv[rbase + 512 + c0 + d4];
        *(float4*)&vb[row * DH + d4] = *(const float4*)&qkv[rbase + 1024 + c0 + d4];
    }
    float qr[DH];
    {
        const float* qrow = &qkv[(size_t)(t0 + tid) * QKVN + c0];
#pragma unroll
        for (int i = 0; i < 16; i++) {
            float4 t4 = *(const float4*)&qrow[i * 4];
            qr[i*4+0] = t4.x * 0.125f; qr[i*4+1] = t4.y * 0.125f;
            qr[i*4+2] = t4.z * 0.125f; qr[i*4+3] = t4.w * 0.125f;
        }
    }
    __syncthreads();

    float* srow = &sb[tid * (BS + 1)];
    float maxv = -1e30f;
    for (int j = 0; j < BS; j++) {
        const float* kr = &kb[j * DH];
        float s = 0.f;
#pragma unroll
        for (int i = 0; i < 16; i++) {
            float4 k4 = *(const float4*)&kr[i * 4];
            s = fmaf(qr[i*4+0], k4.x, s); s = fmaf(qr[i*4+1], k4.y, s);
            s = fmaf(qr[i*4+2], k4.z, s); s = fmaf(qr[i*4+3], k4.w, s);
        }
        srow[j] = s;
        maxv = fmaxf(maxv, s);
    }
    float sum = 0.f;
    for (int j = 0; j < BS; j++) {
        float e = __expf(srow[j] - maxv);
        srow[j] = e; sum += e;
    }
    float inv = 1.0f / sum;

    float acc[DH];
#pragma unroll
    for (int i = 0; i < DH; i++) acc[i] = 0.f;
    for (int j = 0; j < BS; j++) {
        float p = srow[j];
        const float* vr = &vb[j * DH];
#pragma unroll
        for (int i = 0; i < 16; i++) {
            float4 v4 = *(const float4*)&vr[i * 4];
            acc[i*4+0] = fmaf(p, v4.x, acc[i*4+0]); acc[i*4+1] = fmaf(p, v4.y, acc[i*4+1]);
            acc[i*4+2] = fmaf(p, v4.z, acc[i*4+2]); acc[i*4+3] = fmaf(p, v4.w, acc[i*4+3]);
        }
    }
    size_t obase = (size_t)(t0 + tid) * DMODEL + c0;
#pragma unroll
    for (int i = 0; i < DH; i += 2) {
        __half2 hh = {__float2half_rn(acc[i] * inv), __float2half_rn(acc[i+1] * inv)};
        *(__half2*)&ctx[obase + i] = hh;
    }
}

// ================= launch =================
extern "C" void kernel_launch(void* const* d_in, const int* in_sizes, int n_in,
                              void* d_out, int out_size)
{
    const float* inputs = (const float*)d_in[0];
    const float* ln1_s  = (const float*)d_in[1];
    const float* ln1_b  = (const float*)d_in[2];
    const float* wq     = (const float*)d_in[3];
    const float* wk     = (const float*)d_in[4];
    const float* wv     = (const float*)d_in[5];
    const float* wo     = (const float*)d_in[6];
    const float* ln2_s  = (const float*)d_in[7];
    const float* ln2_b  = (const float*)d_in[8];
    const float* w1     = (const float*)d_in[9];
    const float* b1     = (const float*)d_in[10];
    const float* w2     = (const float*)d_in[11];
    const float* b2     = (const float*)d_in[12];
    float* out = (float*)d_out;

    void *xin, *qkv, *ctx, *xb, *yb, *hb;
    void *wqkvh,*wqkvl,*woh,*wol,*w1h,*w1l,*w2h,*w2l;
    cudaGetSymbolAddress(&xin, g_xin); cudaGetSymbolAddress(&qkv, g_qkv);
    cudaGetSymbolAddress(&ctx, g_ctx); cudaGetSymbolAddress(&xb, g_x);
    cudaGetSymbolAddress(&yb, g_y);    cudaGetSymbolAddress(&hb, g_h);
    cudaGetSymbolAddress(&wqkvh, g_wqkv_hi); cudaGetSymbolAddress(&wqkvl, g_wqkv_lo);
    cudaGetSymbolAddress(&woh, g_wo_hi); cudaGetSymbolAddress(&wol, g_wo_lo);
    cudaGetSymbolAddress(&w1h, g_w1_hi); cudaGetSymbolAddress(&w1l, g_w1_lo);
    cudaGetSymbolAddress(&w2h, g_w2_hi); cudaGetSymbolAddress(&w2l, g_w2_lo);

    cudaFuncSetAttribute(mma_gemm<0,0,0,0>, cudaFuncAttributeMaxDynamicSharedMemorySize, GEMM_SMEM);
    cudaFuncSetAttribute(mma_gemm<0,0,1,0>, cudaFuncAttributeMaxDynamicSharedMemorySize, GEMM_SMEM);
    cudaFuncSetAttribute(mma_gemm<1,1,0,1>, cudaFuncAttributeMaxDynamicSharedMemorySize, GEMM_SMEM);
    cudaFuncSetAttribute(mma_gemm<1,0,1,0>, cudaFuncAttributeMaxDynamicSharedMemorySize, GEMM_SMEM);
    cudaFuncSetAttribute(attn_kernel, cudaFuncAttributeMaxDynamicSharedMemorySize, (int)ATTN_SMEM);

    // 0. weight preparation
    int nq = DMODEL*DMODEL/4;
    wsplit_qkv_kernel<<<(nq+255)/256, 256>>>(wq, (__half*)wqkvh, (__half*)wqkvl, 0);
    wsplit_qkv_kernel<<<(nq+255)/256, 256>>>(wk, (__half*)wqkvh, (__half*)wqkvl, 512);
    wsplit_qkv_kernel<<<(nq+255)/256, 256>>>(wv, (__half*)wqkvh, (__half*)wqkvl, 1024);
    wsplit_kernel<<<(nq+255)/256, 256>>>(wo, (__half*)woh, (__half*)wol, DMODEL*DMODEL);
    wsplit_kernel<<<(DMODEL*MLPD/4+255)/256, 256>>>(w1, (__half*)w1h, (__half*)w1l, DMODEL*MLPD);
    wsplit_kernel<<<(DMODEL*MLPD/4+255)/256, 256>>>(w2, (__half*)w2h, (__half*)w2l, DMODEL*MLPD);

    // 1. LN1 -> fp16
    ln_h_kernel<<<TOK/8, 256>>>(inputs, ln1_s, ln1_b, (__half*)xin);

    // 2. fused QKV  (M=TOK, N=1536, K=512)
    dim3 gqkv(QKVN/128, TOK/128);
    mma_gemm<0,0,0,0><<<gqkv, 128, GEMM_SMEM>>>((__half*)xin, (__half*)wqkvh, (__half*)wqkvl,
        nullptr, nullptr, (float*)qkv, nullptr, QKVN, DMODEL);

    // 3. attention
    attn_kernel<<<4 * NBLK * NH, 128, ATTN_SMEM>>>((const float*)qkv, (__half*)ctx);

    // 4. O proj + residual -> x (fp32)
    dim3 gd(DMODEL/128, TOK/128);
    mma_gemm<0,0,1,0><<<gd, 128, GEMM_SMEM>>>((__half*)ctx, (__half*)woh, (__half*)wol,
        nullptr, inputs, (float*)xb, nullptr, DMODEL, DMODEL);

    // 5. LN2 -> fp16
    ln_h_kernel<<<TOK/8, 256>>>((const float*)xb, ln2_s, ln2_b, (__half*)yb);

    // 6. MLP up + bias + gelu -> fp16 h  (N=2048, K=512)
    dim3 gm(MLPD/128, TOK/128);
    mma_gemm<1,1,0,1><<<gm, 128, GEMM_SMEM>>>((__half*)yb, (__half*)w1h, (__half*)w1l,
        b1, nullptr, nullptr, (__half*)hb, MLPD, DMODEL);

    // 7. MLP down + bias + residual -> out  (N=512, K=2048)
    mma_gemm<1,0,1,0><<<gd, 128, GEMM_SMEM>>>((__half*)hb, (__half*)w2h, (__half*)w2l,
        b2, (const float*)xb, out, nullptr, DMODEL, MLPD);
}

// round 6
// speedup vs baseline: 3.5528x; 1.3163x over previous
#include <cuda_runtime.h>
#include <cuda_fp16.h>
#include <math.h>
#include <stdint.h>

#define TOK   (4*4096)
#define DMODEL 512
#define QKVN  1536
#define MLPD   2048
#define NH     8
#define DH     64
#define BS     128
#define NBLK   32

// ================= scratch =================
__device__ __half g_xin[TOK*DMODEL];          // LN1 out, fp16
__device__ float  g_qkv[TOK*QKVN];            // q|k|v fused, fp32
__device__ __half g_ctx[TOK*DMODEL];          // attention out, fp16
__device__ float  g_x  [TOK*DMODEL];          // attn + residual, fp32
__device__ __half g_y  [TOK*DMODEL];          // LN2 out, fp16
__device__ __half g_h  [TOK*MLPD];            // MLP hidden, fp16
// weights: single fp16, native [K,N] layout
__device__ __half g_wqkv[DMODEL*QKVN];
__device__ __half g_wo  [DMODEL*DMODEL];
__device__ __half g_w1  [DMODEL*MLPD];
__device__ __half g_w2  [MLPD*DMODEL];

// ================= small helpers =================
__device__ __forceinline__ uint32_t smem_cast(const void* p) {
    return (uint32_t)__cvta_generic_to_shared(p);
}
__device__ __forceinline__ void cp16(uint32_t s, const void* g) {
    asm volatile("cp.async.cg.shared.global [%0], [%1], 16;" :: "r"(s), "l"(g));
}
#define CP_COMMIT() asm volatile("cp.async.commit_group;")
#define CP_WAIT(n)  asm volatile("cp.async.wait_group %0;" :: "n"(n))

__device__ __forceinline__ void ldsm4(uint32_t* r, uint32_t a) {
    asm volatile("ldmatrix.sync.aligned.m8n8.x4.shared.b16 {%0,%1,%2,%3}, [%4];"
                 : "=r"(r[0]), "=r"(r[1]), "=r"(r[2]), "=r"(r[3]) : "r"(a));
}
__device__ __forceinline__ void ldsm4t(uint32_t* r, uint32_t a) {
    asm volatile("ldmatrix.sync.aligned.m8n8.x4.trans.shared.b16 {%0,%1,%2,%3}, [%4];"
                 : "=r"(r[0]), "=r"(r[1]), "=r"(r[2]), "=r"(r[3]) : "r"(a));
}
__device__ __forceinline__ void mma16816(float* d, const uint32_t* a, const uint32_t* b) {
    asm volatile("mma.sync.aligned.m16n8k16.row.col.f32.f16.f16.f32 "
                 "{%0,%1,%2,%3},{%4,%5,%6,%7},{%8,%9},{%0,%1,%2,%3};"
                 : "+f"(d[0]), "+f"(d[1]), "+f"(d[2]), "+f"(d[3])
                 : "r"(a[0]), "r"(a[1]), "r"(a[2]), "r"(a[3]), "r"(b[0]), "r"(b[1]));
}

__device__ __forceinline__ float gelu_f(float x) {
    float x3 = x * x * x;
    return 0.5f * x * (1.0f + tanhf(0.7978845608028654f * (x + 0.044715f * x3)));
}

// ================= weight convert kernels =================
__global__ void wconv_kernel(const float* __restrict__ w, __half* __restrict__ o, int n)
{
    int i = (blockIdx.x * 256 + threadIdx.x) * 4;
    if (i >= n) return;
    float4 v = *(const float4*)&w[i];
    __half2 p0 = {__float2half_rn(v.x), __float2half_rn(v.y)};
    __half2 p1 = {__float2half_rn(v.z), __float2half_rn(v.w)};
    *(__half2*)&o[i]   = p0;
    *(__half2*)&o[i+2] = p1;
}

// qkv pack: w[512,512] f32 -> wqkv [512,1536] fp16 at column offset
__global__ void wconv_qkv_kernel(const float* __restrict__ w, __half* __restrict__ o, int coff)
{
    int i = (blockIdx.x * 256 + threadIdx.x) * 4;
    if (i >= DMODEL*DMODEL) return;
    int k = i / DMODEL, n = i % DMODEL;
    float4 v = *(const float4*)&w[i];
    size_t off = (size_t)k * QKVN + coff + n;
    __half2 p0 = {__float2half_rn(v.x), __float2half_rn(v.y)};
    __half2 p1 = {__float2half_rn(v.z), __float2half_rn(v.w)};
    *(__half2*)&o[off]   = p0;
    *(__half2*)&o[off+2] = p1;
}

// ================= LayerNorm -> fp16 =================
__global__ void ln_h_kernel(const float* __restrict__ x,
                            const float* __restrict__ scale,
                            const float* __restrict__ bias,
                            __half* __restrict__ out)
{
    int warp = (blockIdx.x * blockDim.x + threadIdx.x) >> 5;
    int lane = threadIdx.x & 31;
    if (warp >= TOK) return;
    const float* row = x + (size_t)warp * DMODEL;

    float4 v[4];
    float sum = 0.f;
#pragma unroll
    for (int i = 0; i < 4; i++) {
        v[i] = *(const float4*)&row[lane*4 + i*128];
        sum += v[i].x + v[i].y + v[i].z + v[i].w;
    }
#pragma unroll
    for (int o = 16; o; o >>= 1) sum += __shfl_xor_sync(0xffffffffu, sum, o);
    float mu = sum * (1.0f / DMODEL);
    float var = 0.f;
#pragma unroll
    for (int i = 0; i < 4; i++) {
        float dx = v[i].x - mu, dy = v[i].y - mu, dz = v[i].z - mu, dw = v[i].w - mu;
        var += dx*dx + dy*dy + dz*dz + dw*dw;
    }
#pragma unroll
    for (int o = 16; o; o >>= 1) var += __shfl_xor_sync(0xffffffffu, var, o);
    float rstd = rsqrtf(var * (1.0f / DMODEL) + 1e-6f);

    size_t base = (size_t)warp * DMODEL;
#pragma unroll
    for (int i = 0; i < 4; i++) {
        int c = lane*4 + i*128;
        float4 sc = *(const float4*)&scale[c];
        float4 bi = *(const float4*)&bias[c];
        float o0 = (v[i].x - mu) * rstd * sc.x + bi.x;
        float o1 = (v[i].y - mu) * rstd * sc.y + bi.y;
        float o2 = (v[i].z - mu) * rstd * sc.z + bi.z;
        float o3 = (v[i].w - mu) * rstd * sc.w + bi.w;
        __half2 p0 = {__float2half_rn(o0), __float2half_rn(o1)};
        __half2 p1 = {__float2half_rn(o2), __float2half_rn(o3)};
        *(__half2*)&out[base + c + 0] = p0;
        *(__half2*)&out[base + c + 2] = p1;
    }
}

// ================= HMMA fp16 single-pass GEMM =================
// C[M,Nc] = A[M,K] * B[K,Nc];  A, B fp16, fp32 accum.
// CTA 128 thr, 4 warps 2x2, warp tile 64x64, CTA tile 128x128, KT=32, 5 stages.
#define KT 32
#define GSTAGES 5
#define A_STRIDE 40
#define B_STRIDE 136
#define A_BYTES (128 * A_STRIDE * 2)
#define B_BYTES (KT * B_STRIDE * 2)
#define STAGE_BYTES (A_BYTES + B_BYTES)
#define GEMM_SMEM (GSTAGES * STAGE_BYTES)

template<int BIAS, int GELU, int RES, int HOUT>
__global__ __launch_bounds__(128, 2)
void mma_gemm(const __half* __restrict__ A, const __half* __restrict__ B,
              const float* __restrict__ bias, const float* __restrict__ res,
              float* __restrict__ Cf, __half* __restrict__ Ch,
              int N, int K)
{
    extern __shared__ char smembuf[];
    const uint32_t sbase = smem_cast(smembuf);
    const int tid = threadIdx.x, warp = tid >> 5, lane = tid & 31;
    const int m0 = blockIdx.y * 128, n0 = blockIdx.x * 128;
    const int T = K / KT;
    const int wm = (warp >> 1) * 64;
    const int wn = (warp & 1) * 64;

    float acc[4][8][4];
#pragma unroll
    for (int i = 0; i < 4; i++)
#pragma unroll
        for (int j = 0; j < 8; j++)
#pragma unroll
            for (int q = 0; q < 4; q++) acc[i][j][q] = 0.f;

    const int a_row = tid >> 2, a_kc = tid & 3;
    const int b_row = tid >> 4, b_nc = tid & 15;

    auto issue = [&](int it) {
        int kk = it * KT;
        uint32_t sA = sbase + (uint32_t)(it % GSTAGES) * STAGE_BYTES;
        uint32_t sB = sA + A_BYTES;
#pragma unroll
        for (int q = 0; q < 4; q++) {
            int row = a_row + q * 32;
            cp16(sA + row * (A_STRIDE * 2) + a_kc * 16,
                 A + (size_t)(m0 + row) * K + kk + a_kc * 8);
        }
#pragma unroll
        for (int q = 0; q < 4; q++) {
            int row = b_row + q * 8;
            cp16(sB + row * (B_STRIDE * 2) + b_nc * 16,
                 B + (size_t)(kk + row) * N + n0 + b_nc * 8);
        }
        CP_COMMIT();
    };

#pragma unroll
    for (int s = 0; s < GSTAGES - 1; s++) issue(s);

    const uint32_t a_off = ((wm + (lane & 15)) * A_STRIDE + (lane >> 4) * 8) * 2;
    const uint32_t b_off = (((lane & 15)) * B_STRIDE + wn + (lane >> 4) * 8) * 2;

    uint32_t af[2][4][4], bf[2][4][4];

    for (int it = 0; it < T; it++) {
        CP_WAIT(3);
        __syncthreads();
        if (it + GSTAGES - 1 < T) issue(it + GSTAGES - 1);

        uint32_t sA = sbase + (uint32_t)(it % GSTAGES) * STAGE_BYTES;
        uint32_t sB = sA + A_BYTES;

#pragma unroll
        for (int mi = 0; mi < 4; mi++)
            ldsm4(af[0][mi], sA + a_off + (mi * 16 * A_STRIDE) * 2);
#pragma unroll
        for (int bi = 0; bi < 4; bi++)
            ldsm4t(bf[0][bi], sB + b_off + (bi * 16) * 2);
#pragma unroll
        for (int mi = 0; mi < 4; mi++)
            ldsm4(af[1][mi], sA + a_off + (mi * 16 * A_STRIDE + 16) * 2);
#pragma unroll
        for (int bi = 0; bi < 4; bi++)
            ldsm4t(bf[1][bi], sB + b_off + (16 * B_STRIDE + bi * 16) * 2);

#pragma unroll
        for (int ks = 0; ks < 2; ks++)
#pragma unroll
            for (int mi = 0; mi < 4; mi++)
#pragma unroll
                for (int ni = 0; ni < 8; ni++)
                    mma16816(acc[mi][ni], af[ks][mi], &bf[ks][ni >> 1][(ni & 1) * 2]);
    }

    // epilogue
#pragma unroll
    for (int mi = 0; mi < 4; mi++) {
#pragma unroll
        for (int r = 0; r < 2; r++) {
            int row = m0 + wm + mi * 16 + r * 8 + (lane >> 2);
#pragma unroll
            for (int ni = 0; ni < 8; ni++) {
                int col = n0 + wn + ni * 8 + (lane & 3) * 2;
                size_t off = (size_t)row * N + col;
                float v0 = acc[mi][ni][r * 2 + 0];
                float v1 = acc[mi][ni][r * 2 + 1];
                if (BIAS) { v0 += bias[col]; v1 += bias[col + 1]; }
                if (GELU) { v0 = gelu_f(v0); v1 = gelu_f(v1); }
                if (RES)  { float2 rr = *(const float2*)&res[off]; v0 += rr.x; v1 += rr.y; }
                if (HOUT) {
                    __half2 hh = {__float2half_rn(v0), __float2half_rn(v1)};
                    *(__half2*)&Ch[off] = hh;
                } else {
                    float2 o = {v0, v1};
                    *(float2*)&Cf[off] = o;
                }
            }
        }
    }
}

// ================= block-local attention (fp32 in from fused qkv, fp16 out) =================
#define ATTN_SMEM ((BS*DH + BS*DH + BS*(BS+1)) * sizeof(float))

__global__ void attn_kernel(const float* __restrict__ qkv,
                            __half* __restrict__ ctx)
{
    extern __shared__ float sm[];
    float* kb = sm;
    float* vb = kb + BS * DH;
    float* sb = vb + BS * DH;

    int bid = blockIdx.x;
    int h   = bid & 7;
    int blk = (bid >> 3) & 31;
    int b   = bid >> 8;
    int t0  = b * 4096 + blk * BS;
    int c0  = h * DH;
    int tid = threadIdx.x;

#pragma unroll
    for (int it = 0; it < 16; it++) {
        int idx = tid + it * 128;
        int row = idx >> 4;
        int d4  = (idx & 15) << 2;
        size_t rbase = (size_t)(t0 + row) * QKVN;
        *(float4*)&kb[row * DH + d4] = *(const float4*)&qkv[rbase + 512 + c0 + d4];
        *(float4*)&vb[row * DH + d4] = *(const float4*)&qkv[rbase + 1024 + c0 + d4];
    }
    float qr[DH];
    {
        const float* qrow = &qkv[(size_t)(t0 + tid) * QKVN + c0];
#pragma unroll
        for (int i = 0; i < 16; i++) {
            float4 t4 = *(const float4*)&qrow[i * 4];
            qr[i*4+0] = t4.x * 0.125f; qr[i*4+1] = t4.y * 0.125f;
            qr[i*4+2] = t4.z * 0.125f; qr[i*4+3] = t4.w * 0.125f;
        }
    }
    __syncthreads();

    float* srow = &sb[tid * (BS + 1)];
    float maxv = -1e30f;
    for (int j = 0; j < BS; j++) {
        const float* kr = &kb[j * DH];
        float s = 0.f;
#pragma unroll
        for (int i = 0; i < 16; i++) {
            float4 k4 = *(const float4*)&kr[i * 4];
            s = fmaf(qr[i*4+0], k4.x, s); s = fmaf(qr[i*4+1], k4.y, s);
            s = fmaf(qr[i*4+2], k4.z, s); s = fmaf(qr[i*4+3], k4.w, s);
        }
        srow[j] = s;
        maxv = fmaxf(maxv, s);
    }
    float sum = 0.f;
    for (int j = 0; j < BS; j++) {
        float e = __expf(srow[j] - maxv);
        srow[j] = e; sum += e;
    }
    float inv = 1.0f / sum;

    float acc[DH];
#pragma unroll
    for (int i = 0; i < DH; i++) acc[i] = 0.f;
    for (int j = 0; j < BS; j++) {
        float p = srow[j];
        const float* vr = &vb[j * DH];
#pragma unroll
        for (int i = 0; i < 16; i++) {
            float4 v4 = *(const float4*)&vr[i * 4];
            acc[i*4+0] = fmaf(p, v4.x, acc[i*4+0]); acc[i*4+1] = fmaf(p, v4.y, acc[i*4+1]);
            acc[i*4+2] = fmaf(p, v4.z, acc[i*4+2]); acc[i*4+3] = fmaf(p, v4.w, acc[i*4+3]);
        }
    }
    size_t obase = (size_t)(t0 + tid) * DMODEL + c0;
#pragma unroll
    for (int i = 0; i < DH; i += 2) {
        __half2 hh = {__float2half_rn(acc[i] * inv), __float2half_rn(acc[i+1] * inv)};
        *(__half2*)&ctx[obase + i] = hh;
    }
}

// ================= launch =================
extern "C" void kernel_launch(void* const* d_in, const int* in_sizes, int n_in,
                              void* d_out, int out_size)
{
    const float* inputs = (const float*)d_in[0];
    const float* ln1_s  = (const float*)d_in[1];
    const float* ln1_b  = (const float*)d_in[2];
    const float* wq     = (const float*)d_in[3];
    const float* wk     = (const float*)d_in[4];
    const float* wv     = (const float*)d_in[5];
    const float* wo     = (const float*)d_in[6];
    const float* ln2_s  = (const float*)d_in[7];
    const float* ln2_b  = (const float*)d_in[8];
    const float* w1     = (const float*)d_in[9];
    const float* b1     = (const float*)d_in[10];
    const float* w2     = (const float*)d_in[11];
    const float* b2     = (const float*)d_in[12];
    float* out = (float*)d_out;

    void *xin, *qkv, *ctx, *xb, *yb, *hb;
    void *wqkvp, *wop, *w1p, *w2p;
    cudaGetSymbolAddress(&xin, g_xin); cudaGetSymbolAddress(&qkv, g_qkv);
    cudaGetSymbolAddress(&ctx, g_ctx); cudaGetSymbolAddress(&xb, g_x);
    cudaGetSymbolAddress(&yb, g_y);    cudaGetSymbolAddress(&hb, g_h);
    cudaGetSymbolAddress(&wqkvp, g_wqkv); cudaGetSymbolAddress(&wop, g_wo);
    cudaGetSymbolAddress(&w1p, g_w1);     cudaGetSymbolAddress(&w2p, g_w2);

    cudaFuncSetAttribute(mma_gemm<0,0,0,0>, cudaFuncAttributeMaxDynamicSharedMemorySize, GEMM_SMEM);
    cudaFuncSetAttribute(mma_gemm<0,0,1,0>, cudaFuncAttributeMaxDynamicSharedMemorySize, GEMM_SMEM);
    cudaFuncSetAttribute(mma_gemm<1,1,0,1>, cudaFuncAttributeMaxDynamicSharedMemorySize, GEMM_SMEM);
    cudaFuncSetAttribute(mma_gemm<1,0,1,0>, cudaFuncAttributeMaxDynamicSharedMemorySize, GEMM_SMEM);
    cudaFuncSetAttribute(attn_kernel, cudaFuncAttributeMaxDynamicSharedMemorySize, (int)ATTN_SMEM);

    // 0. weight conversion
    int nq = DMODEL*DMODEL/4;
    wconv_qkv_kernel<<<(nq+255)/256, 256>>>(wq, (__half*)wqkvp, 0);
    wconv_qkv_kernel<<<(nq+255)/256, 256>>>(wk, (__half*)wqkvp, 512);
    wconv_qkv_kernel<<<(nq+255)/256, 256>>>(wv, (__half*)wqkvp, 1024);
    wconv_kernel<<<(nq+255)/256, 256>>>(wo, (__half*)wop, DMODEL*DMODEL);
    wconv_kernel<<<(DMODEL*MLPD/4+255)/256, 256>>>(w1, (__half*)w1p, DMODEL*MLPD);
    wconv_kernel<<<(DMODEL*MLPD/4+255)/256, 256>>>(w2, (__half*)w2p, DMODEL*MLPD);

    // 1. LN1 -> fp16
    ln_h_kernel<<<TOK/8, 256>>>(inputs, ln1_s, ln1_b, (__half*)xin);

    // 2. fused QKV  (M=TOK, N=1536, K=512)
    dim3 gqkv(QKVN/128, TOK/128);
    mma_gemm<0,0,0,0><<<gqkv, 128, GEMM_SMEM>>>((__half*)xin, (__half*)wqkvp,
        nullptr, nullptr, (float*)qkv, nullptr, QKVN, DMODEL);

    // 3. attention
    attn_kernel<<<4 * NBLK * NH, 128, ATTN_SMEM>>>((const float*)qkv, (__half*)ctx);

    // 4. O proj + residual -> x (fp32)
    dim3 gd(DMODEL/128, TOK/128);
    mma_gemm<0,0,1,0><<<gd, 128, GEMM_SMEM>>>((__half*)ctx, (__half*)wop,
        nullptr, inputs, (float*)xb, nullptr, DMODEL, DMODEL);

    // 5. LN2 -> fp16
    ln_h_kernel<<<TOK/8, 256>>>((const float*)xb, ln2_s, ln2_b, (__half*)yb);

    // 6. MLP up + bias + gelu -> fp16 h  (N=2048, K=512)
    dim3 gm(MLPD/128, TOK/128);
    mma_gemm<1,1,0,1><<<gm, 128, GEMM_SMEM>>>((__half*)yb, (__half*)w1p,
        b1, nullptr, nullptr, (__half*)hb, MLPD, DMODEL);

    // 7. MLP down + bias + residual -> out  (N=512, K=2048)
    mma_gemm<1,0,1,0><<<gd, 128, GEMM_SMEM>>>((__half*)hb, (__half*)w2p,
        b2, (const float*)xb, out, nullptr, DMODEL, MLPD);
}